// round 12
// baseline (speedup 1.0000x reference)
#include <cuda_runtime.h>
#include <cuda_fp16.h>
#include <cstdint>

// LSTM extractor via warp-MMA (HMMA m16n8k16, fp16 in / fp32 accum).
//   B=2048, T=256, D=32, H=256, F=256.
// 64 CTAs x 512 threads, CTA owns M=32 batch rows for the whole recurrence.
// Warp w owns hidden units [16w,16w+16): 8 n8-tiles; all 4 gates of a given
// (row,u) land in the same thread -> gate fusion + c-state in registers.
// R11: software-pipelined weight LDGs (double-buffer, full unroll),
//      double-buffered A smem -> single __syncthreads per step,
//      x(t+1) prefetched into regs at step top.

#define NKC     18      // K chunks of 16 (K = 288 = 32 x + 256 h)
#define ASTRIDE 296     // halves per A row (592B), conflict-free for ldmatrix
#define NWARP   16
#define NCTA    64      // 2048 / 32 rows

__device__ uint4 g_Wfrag[NWARP * NKC * 4 * 32];   // fp16 fragment-major
__device__ uint4 g_WfcFrag[NWARP * 16 * 32];

__device__ __forceinline__ float tanhap(float x) {
    float r;
    asm("tanh.approx.f32 %0, %1;" : "=f"(r) : "f"(x));
    return r;
}
__device__ __forceinline__ float sigap(float x) {
    return fmaf(tanhap(0.5f * x), 0.5f, 0.5f);
}

__device__ __forceinline__ uint32_t smemu32(const void* p) {
    uint32_t a;
    asm("{ .reg .u64 t; cvta.to.shared.u64 t, %1; cvt.u32.u64 %0, t; }"
        : "=r"(a) : "l"(p));
    return a;
}

#define LDMATRIX_X4(a0, a1, a2, a3, addr)                                   \
    asm volatile("ldmatrix.sync.aligned.m8n8.x4.shared.b16 {%0,%1,%2,%3}, [%4];" \
                 : "=r"(a0), "=r"(a1), "=r"(a2), "=r"(a3) : "r"(addr))

#define MMA16816(d, a0, a1, a2, a3, b0, b1)                                 \
    asm volatile("mma.sync.aligned.m16n8k16.row.col.f32.f16.f16.f32 "       \
                 "{%0,%1,%2,%3},{%4,%5,%6,%7},{%8,%9},{%0,%1,%2,%3};"       \
                 : "+f"(d[0]), "+f"(d[1]), "+f"(d[2]), "+f"(d[3])           \
                 : "r"(a0), "r"(a1), "r"(a2), "r"(a3), "r"(b0), "r"(b1))

// ---------------- prep: weights -> fp16 fragment-major layouts ------------
__device__ __forceinline__ float wval(const float* W_ih, const float* W_hh,
                                      int col, int k) {
    return (k < 32) ? W_ih[col * 32 + k] : W_hh[col * 256 + (k - 32)];
}

__global__ void prep_kernel(const float* __restrict__ W_ih,
                            const float* __restrict__ W_hh,
                            const float* __restrict__ W_fc) {
    int g = blockIdx.x * 256 + threadIdx.x;
    union { __half h[8]; uint4 v; } u;
    if (g < NWARP * NKC * 4 * 32) {
        int l = g & 31;
        int t = g >> 5;
        int q = t & 3;  t >>= 2;
        int kc = t % NKC;
        int w  = t / NKC;
        int k0 = kc * 16 + (l & 3) * 2;
        int n  = l >> 2;
        for (int s = 0; s < 2; s++) {
            int tt = 2 * q + s;
            int gate = tt >> 1, ut = tt & 1;
            int col = gate * 256 + w * 16 + ut * 8 + n;
            u.h[s * 4 + 0] = __float2half(wval(W_ih, W_hh, col, k0));
            u.h[s * 4 + 1] = __float2half(wval(W_ih, W_hh, col, k0 + 1));
            u.h[s * 4 + 2] = __float2half(wval(W_ih, W_hh, col, k0 + 8));
            u.h[s * 4 + 3] = __float2half(wval(W_ih, W_hh, col, k0 + 9));
        }
        g_Wfrag[g] = u.v;
    } else if (g < NWARP * NKC * 4 * 32 + NWARP * 16 * 32) {
        int g2 = g - NWARP * NKC * 4 * 32;
        int l = g2 & 31;
        int t = g2 >> 5;
        int kc = t & 15;
        int w  = t >> 4;
        int k0 = kc * 16 + (l & 3) * 2;
        int n  = l >> 2;
        for (int s = 0; s < 2; s++) {            // ut = s
            int col = w * 16 + s * 8 + n;
            u.h[s * 4 + 0] = __float2half(W_fc[col * 256 + k0]);
            u.h[s * 4 + 1] = __float2half(W_fc[col * 256 + k0 + 1]);
            u.h[s * 4 + 2] = __float2half(W_fc[col * 256 + k0 + 8]);
            u.h[s * 4 + 3] = __float2half(W_fc[col * 256 + k0 + 9]);
        }
        g_WfcFrag[g2] = u.v;
    }
}

// ---------------- main persistent LSTM + FC kernel ------------------------
__global__ void __launch_bounds__(512, 1)
lstm_kernel(const float* __restrict__ obs,
            const float* __restrict__ b_ih,
            const float* __restrict__ b_hh,
            const float* __restrict__ b_fc,
            float* __restrict__ out) {
    __shared__ __align__(16) __half hA[2][32 * ASTRIDE];  // double-buffered A
    __shared__ float bias_s[1024];

    const int tid  = threadIdx.x;
    const int w    = tid >> 5;
    const int l    = tid & 31;
    const int gid  = l >> 2;
    const int tid4 = l & 3;
    const int b0   = blockIdx.x * 32;

    bias_s[tid]       = b_ih[tid]       + b_hh[tid];
    bias_s[tid + 512] = b_ih[tid + 512] + b_hh[tid + 512];

    // zero only buf0 (buf1 is fully written during iteration 0)
    for (int i = tid; i < 32 * ASTRIDE; i += 512)
        hA[0][i] = __float2half(0.0f);

    // x-staging role: thread -> (row, feature pair)
    const int xrow = tid >> 4;
    const int xdp  = (tid & 15) * 2;
    const float* xptr = obs + (size_t)(b0 + xrow) * 8192 + xdp;
    {   // stage x(0) into buf0
        float2 x2 = *(const float2*)xptr;
        *(__half2*)&hA[0][xrow * ASTRIDE + xdp] = __float22half2_rn(x2);
    }
    __syncthreads();

    float c[16];
#pragma unroll
    for (int i = 0; i < 16; i++) c[i] = 0.0f;

    const uint4* __restrict__ wbase = g_Wfrag + w * (NKC * 4 * 32) + l;
    const uint32_t aoff =
        (uint32_t)(((l & 15) * ASTRIDE + (l >> 4) * 8) * 2);
    const uint32_t aBase[2] = { smemu32(hA[0]) + aoff, smemu32(hA[1]) + aoff };

    // per-thread biases held in regs
    float2 bsv[8];
#pragma unroll
    for (int tt = 0; tt < 8; tt++) {
        int gate = tt >> 1, ut = tt & 1;
        bsv[tt] = *(const float2*)&bias_s[gate * 256 + w * 16 + ut * 8 + tid4 * 2];
    }

#pragma unroll 1
    for (int t = 0; t < 256; t++) {
        const uint32_t aR = aBase[t & 1];
        __half* __restrict__ bufW = hA[(t + 1) & 1];

        // prefetch x(t+1) into regs (overlaps GEMM)
        float2 xnext;
        if (t < 255) xnext = *(const float2*)(xptr + (size_t)(t + 1) * 32);

        float acc[2][8][4];
#pragma unroll
        for (int tt = 0; tt < 8; tt++)
#pragma unroll
            for (int mt = 0; mt < 2; mt++) {
                acc[mt][tt][0] = bsv[tt].x; acc[mt][tt][1] = bsv[tt].y;
                acc[mt][tt][2] = bsv[tt].x; acc[mt][tt][3] = bsv[tt].y;
            }

        // software-pipelined GEMM over K chunks
        uint4 Bb[2][4];
#pragma unroll
        for (int q = 0; q < 4; q++) Bb[0][q] = __ldg(wbase + q * 32);

#pragma unroll
        for (int kc = 0; kc < NKC; kc++) {
            if (kc + 1 < NKC) {
                const uint4* wn = wbase + ((kc + 1) * 4) * 32;
#pragma unroll
                for (int q = 0; q < 4; q++)
                    Bb[(kc + 1) & 1][q] = __ldg(wn + q * 32);
            }
            const uint4 B0 = Bb[kc & 1][0];
            const uint4 B1 = Bb[kc & 1][1];
            const uint4 B2 = Bb[kc & 1][2];
            const uint4 B3 = Bb[kc & 1][3];
#pragma unroll
            for (int mt = 0; mt < 2; mt++) {
                uint32_t a0, a1, a2, a3;
                LDMATRIX_X4(a0, a1, a2, a3,
                            aR + (uint32_t)((mt * 16 * ASTRIDE + kc * 16) * 2));
                MMA16816(acc[mt][0], a0, a1, a2, a3, B0.x, B0.y);
                MMA16816(acc[mt][1], a0, a1, a2, a3, B0.z, B0.w);
                MMA16816(acc[mt][2], a0, a1, a2, a3, B1.x, B1.y);
                MMA16816(acc[mt][3], a0, a1, a2, a3, B1.z, B1.w);
                MMA16816(acc[mt][4], a0, a1, a2, a3, B2.x, B2.y);
                MMA16816(acc[mt][5], a0, a1, a2, a3, B2.z, B2.w);
                MMA16816(acc[mt][6], a0, a1, a2, a3, B3.x, B3.y);
                MMA16816(acc[mt][7], a0, a1, a2, a3, B3.z, B3.w);
            }
        }

        // gates + state update; publish h_{t+1} into the OTHER buffer
#pragma unroll
        for (int mt = 0; mt < 2; mt++) {
#pragma unroll
            for (int ut = 0; ut < 2; ut++) {
#pragma unroll
                for (int jr = 0; jr < 2; jr++) {
                    int j = 2 * jr;
                    int ci = (mt * 2 + ut) * 4 + j;
                    float i0 = sigap(acc[mt][0 + ut][j]);
                    float i1 = sigap(acc[mt][0 + ut][j + 1]);
                    float f0 = sigap(acc[mt][2 + ut][j]);
                    float f1 = sigap(acc[mt][2 + ut][j + 1]);
                    float g0 = tanhap(acc[mt][4 + ut][j]);
                    float g1 = tanhap(acc[mt][4 + ut][j + 1]);
                    float o0 = sigap(acc[mt][6 + ut][j]);
                    float o1 = sigap(acc[mt][6 + ut][j + 1]);
                    float c0 = fmaf(f0, c[ci],     i0 * g0);
                    float c1 = fmaf(f1, c[ci + 1], i1 * g1);
                    c[ci] = c0; c[ci + 1] = c1;
                    float h0 = o0 * tanhap(c0);
                    float h1 = o1 * tanhap(c1);
                    int row = mt * 16 + gid + jr * 8;
                    int u   = w * 16 + ut * 8 + tid4 * 2;
                    *(__half2*)&bufW[row * ASTRIDE + 32 + u] =
                        __floats2half2_rn(h0, h1);
                }
            }
        }

        // stage x(t+1) into the OTHER buffer
        if (t < 255)
            *(__half2*)&bufW[xrow * ASTRIDE + xdp] = __float22half2_rn(xnext);

        __syncthreads();   // single barrier: bufW complete, bufR free
    }

    // ---- FC: out[b][f] = h_last . W_fc[f][:] + b_fc[f] ----
    // h_256 lives in buf[(255+1)&1] = buf0.
    const uint32_t aF = aBase[0];
    float accf[2][2][4];
#pragma unroll
    for (int mt = 0; mt < 2; mt++)
#pragma unroll
        for (int ut = 0; ut < 2; ut++)
#pragma unroll
            for (int j = 0; j < 4; j++) accf[mt][ut][j] = 0.0f;

    const uint4* __restrict__ fbase = g_WfcFrag + w * (16 * 32) + l;
#pragma unroll 2
    for (int kc = 0; kc < 16; kc++) {
        uint4 B = __ldg(fbase + kc * 32);
#pragma unroll
        for (int mt = 0; mt < 2; mt++) {
            uint32_t a0, a1, a2, a3;
            LDMATRIX_X4(a0, a1, a2, a3,
                        aF + (uint32_t)((mt * 16 * ASTRIDE + 32 + kc * 16) * 2));
            MMA16816(accf[mt][0], a0, a1, a2, a3, B.x, B.y);
            MMA16816(accf[mt][1], a0, a1, a2, a3, B.z, B.w);
        }
    }

#pragma unroll
    for (int mt = 0; mt < 2; mt++) {
#pragma unroll
        for (int ut = 0; ut < 2; ut++) {
            int col = w * 16 + ut * 8 + tid4 * 2;
            float2 bf = *(const float2*)&b_fc[col];
#pragma unroll
            for (int jr = 0; jr < 2; jr++) {
                int row = b0 + mt * 16 + gid + jr * 8;
                float2 r;
                r.x = accf[mt][ut][2 * jr]     + bf.x;
                r.y = accf[mt][ut][2 * jr + 1] + bf.y;
                *(float2*)&out[(size_t)row * 256 + col] = r;
            }
        }
    }
}

extern "C" void kernel_launch(void* const* d_in, const int* in_sizes, int n_in,
                              void* d_out, int out_size) {
    const float* obs  = (const float*)d_in[0];  // [2048,256,32]
    const float* W_ih = (const float*)d_in[1];  // [1024,32]
    const float* W_hh = (const float*)d_in[2];  // [1024,256]
    const float* b_ih = (const float*)d_in[3];  // [1024]
    const float* b_hh = (const float*)d_in[4];  // [1024]
    const float* W_fc = (const float*)d_in[5];  // [256,256]
    const float* b_fc = (const float*)d_in[6];  // [256]
    float* out = (float*)d_out;                 // [2048,256]

    int total = NWARP * NKC * 4 * 32 + NWARP * 16 * 32;   // 45056
    prep_kernel<<<(total + 255) / 256, 256>>>(W_ih, W_hh, W_fc);
    lstm_kernel<<<NCTA, 512>>>(obs, b_ih, b_hh, b_fc, out);
}

// round 13
// speedup vs baseline: 1.9559x; 1.9559x over previous
#include <cuda_runtime.h>
#include <cuda_fp16.h>
#include <cstdint>

// LSTM extractor, HMMA m16n8k16 fp16/fp32, cluster-2 N-split.
//   B=2048, T=256, D=32, H=256, F=256.
// 128 CTAs (64 clusters of 2) x 512 threads. Cluster owns M=32 batch rows;
// CTA rank r computes all 4 gates for hidden units [128r, 128r+128).
// Each CTA keeps a full local fp16 A=(x|h) copy; after activations it writes
// its h-half to its own AND the peer's next A buffer (DSMEM), then one
// barrier.cluster per step. Warp owns 8 units (slot s = 16*rank + w).

#define NKC     18      // K chunks of 16 (K = 288 = 32 x + 256 h)
#define ASTRIDE 296     // halves per A row (592B)
#define NSLOT   32      // 8-unit slots across the cluster
#define NCTA    128

__device__ uint4 g_W2[NSLOT * NKC * 2 * 32];   // per-slot fragment-major
__device__ uint2 g_Wfc2[NSLOT * 16 * 32];

__device__ __forceinline__ float tanhap(float x) {
    float r;
    asm("tanh.approx.f32 %0, %1;" : "=f"(r) : "f"(x));
    return r;
}
__device__ __forceinline__ float sigap(float x) {
    return fmaf(tanhap(0.5f * x), 0.5f, 0.5f);
}

__device__ __forceinline__ uint32_t smemu32(const void* p) {
    uint32_t a;
    asm("{ .reg .u64 t; cvta.to.shared.u64 t, %1; cvt.u32.u64 %0, t; }"
        : "=r"(a) : "l"(p));
    return a;
}
__device__ __forceinline__ uint32_t mapa_u32(uint32_t addr, uint32_t r) {
    uint32_t o;
    asm("mapa.shared::cluster.u32 %0, %1, %2;" : "=r"(o) : "r"(addr), "r"(r));
    return o;
}

#define CLUSTER_SYNC() do {                                                 \
    asm volatile("barrier.cluster.arrive.aligned;" ::: "memory");           \
    asm volatile("barrier.cluster.wait.aligned;" ::: "memory");             \
} while (0)

#define LDMATRIX_X4(a0, a1, a2, a3, addr)                                   \
    asm volatile("ldmatrix.sync.aligned.m8n8.x4.shared.b16 {%0,%1,%2,%3}, [%4];" \
                 : "=r"(a0), "=r"(a1), "=r"(a2), "=r"(a3) : "r"(addr))

#define MMA16816(d, a0, a1, a2, a3, b0, b1)                                 \
    asm volatile("mma.sync.aligned.m16n8k16.row.col.f32.f16.f16.f32 "       \
                 "{%0,%1,%2,%3},{%4,%5,%6,%7},{%8,%9},{%0,%1,%2,%3};"       \
                 : "+f"(d[0]), "+f"(d[1]), "+f"(d[2]), "+f"(d[3])           \
                 : "r"(a0), "r"(a1), "r"(a2), "r"(a3), "r"(b0), "r"(b1))

// ---------------- prep: weights -> per-slot fp16 fragment layouts ---------
__device__ __forceinline__ float wval(const float* W_ih, const float* W_hh,
                                      int col, int k) {
    return (k < 32) ? W_ih[col * 32 + k] : W_hh[col * 256 + (k - 32)];
}

__global__ void prep_kernel(const float* __restrict__ W_ih,
                            const float* __restrict__ W_hh,
                            const float* __restrict__ W_fc) {
    int g = blockIdx.x * 256 + threadIdx.x;
    if (g < NSLOT * NKC * 2 * 32) {                 // 36864
        int l = g & 31;
        int t = g >> 5;
        int q = t & 1;  t >>= 1;
        int kc = t % NKC;
        int s  = t / NKC;
        int k0 = kc * 16 + (l & 3) * 2;
        int n  = l >> 2;
        union { __half h[8]; uint4 v; } u;
        for (int hf = 0; hf < 2; hf++) {
            int gate = 2 * q + hf;                  // 0=i 1=f 2=g 3=o
            int col = gate * 256 + s * 8 + n;
            u.h[hf * 4 + 0] = __float2half(wval(W_ih, W_hh, col, k0));
            u.h[hf * 4 + 1] = __float2half(wval(W_ih, W_hh, col, k0 + 1));
            u.h[hf * 4 + 2] = __float2half(wval(W_ih, W_hh, col, k0 + 8));
            u.h[hf * 4 + 3] = __float2half(wval(W_ih, W_hh, col, k0 + 9));
        }
        g_W2[g] = u.v;
    } else if (g < NSLOT * NKC * 2 * 32 + NSLOT * 16 * 32) {   // +16384
        int g2 = g - NSLOT * NKC * 2 * 32;
        int l = g2 & 31;
        int t = g2 >> 5;
        int kc = t & 15;
        int s  = t >> 4;
        int k0 = kc * 16 + (l & 3) * 2;
        int n  = l >> 2;
        int col = s * 8 + n;
        union { __half h[4]; uint2 v; } u;
        u.h[0] = __float2half(W_fc[col * 256 + k0]);
        u.h[1] = __float2half(W_fc[col * 256 + k0 + 1]);
        u.h[2] = __float2half(W_fc[col * 256 + k0 + 8]);
        u.h[3] = __float2half(W_fc[col * 256 + k0 + 9]);
        g_Wfc2[g2] = u.v;
    }
}

// ---------------- main persistent LSTM + FC kernel ------------------------
__global__ void __launch_bounds__(512, 1) __cluster_dims__(2, 1, 1)
lstm_kernel(const float* __restrict__ obs,
            const float* __restrict__ b_ih,
            const float* __restrict__ b_hh,
            const float* __restrict__ b_fc,
            float* __restrict__ out) {
    __shared__ __align__(16) __half hA[2][32 * ASTRIDE];  // double-buffered A
    __shared__ float bias_s[1024];

    const int tid  = threadIdx.x;
    const int w    = tid >> 5;
    const int l    = tid & 31;
    const int gid  = l >> 2;
    const int tid4 = l & 3;

    uint32_t rank;
    asm("mov.u32 %0, %%cluster_ctarank;" : "=r"(rank));
    const int s  = (int)rank * 16 + w;     // global 8-unit slot
    const int b0 = (blockIdx.x >> 1) * 32; // cluster's first batch row

    bias_s[tid]       = b_ih[tid]       + b_hh[tid];
    bias_s[tid + 512] = b_ih[tid + 512] + b_hh[tid + 512];

    // zero buf0 (h must start at 0); buf1 fully written during step 0
    for (int i = tid; i < 32 * ASTRIDE; i += 512)
        hA[0][i] = __float2half(0.0f);

    // x staging role: thread -> (row, feature pair)
    const int xrow = tid >> 4;
    const int xdp  = (tid & 15) * 2;
    const float* xptr = obs + (size_t)(b0 + xrow) * 8192 + xdp;
    {   // stage x(0) into buf0 (local copy; both CTAs do this)
        float2 x2 = *(const float2*)xptr;
        *(__half2*)&hA[0][xrow * ASTRIDE + xdp] = __float22half2_rn(x2);
    }
    __syncthreads();

    const uint32_t locA0 = smemu32(hA[0]);
    const uint32_t locA1 = smemu32(hA[1]);
    uint32_t peerA[2];
    peerA[0] = mapa_u32(locA0, rank ^ 1u);
    peerA[1] = mapa_u32(locA1, rank ^ 1u);

    float c[8];
#pragma unroll
    for (int i = 0; i < 8; i++) c[i] = 0.0f;

    const uint4* __restrict__ wbase = g_W2 + (s * NKC * 2) * 32 + l;
    const uint32_t aoff = (uint32_t)(((l & 15) * ASTRIDE + (l >> 4) * 8) * 2);
    const uint32_t aBase[2] = { locA0 + aoff, locA1 + aoff };

    float2 bsv[4];
#pragma unroll
    for (int gate = 0; gate < 4; gate++)
        bsv[gate] = *(const float2*)&bias_s[gate * 256 + s * 8 + tid4 * 2];

    const int ucol = s * 8 + tid4 * 2;     // my h columns (pair)

#pragma unroll 1
    for (int t = 0; t < 256; t++) {
        const uint32_t aR = aBase[t & 1];
        const int wb = (t + 1) & 1;
        __half* __restrict__ bufW = hA[wb];
        const uint32_t peerW = peerA[wb];

        // prefetch x(t+1) (overlaps GEMM)
        float2 xnext;
        if (t < 255) xnext = *(const float2*)(xptr + (size_t)(t + 1) * 32);

        float acc[2][4][4];
#pragma unroll
        for (int mt = 0; mt < 2; mt++)
#pragma unroll
            for (int gate = 0; gate < 4; gate++) {
                acc[mt][gate][0] = bsv[gate].x; acc[mt][gate][1] = bsv[gate].y;
                acc[mt][gate][2] = bsv[gate].x; acc[mt][gate][3] = bsv[gate].y;
            }

        // distance-2 software-pipelined weight fetch
        uint4 Bq[2][2];
        Bq[0][0] = __ldg(wbase +  0);
        Bq[0][1] = __ldg(wbase + 32);
        Bq[1][0] = __ldg(wbase + 64);
        Bq[1][1] = __ldg(wbase + 96);

#pragma unroll
        for (int kc = 0; kc < NKC; kc++) {
            const uint4 B0 = Bq[kc & 1][0];
            const uint4 B1 = Bq[kc & 1][1];
            if (kc + 2 < NKC) {
                const uint4* wn = wbase + ((kc + 2) * 2) * 32;
                Bq[kc & 1][0] = __ldg(wn);
                Bq[kc & 1][1] = __ldg(wn + 32);
            }
#pragma unroll
            for (int mt = 0; mt < 2; mt++) {
                uint32_t a0, a1, a2, a3;
                LDMATRIX_X4(a0, a1, a2, a3,
                            aR + (uint32_t)((mt * 16 * ASTRIDE + kc * 16) * 2));
                MMA16816(acc[mt][0], a0, a1, a2, a3, B0.x, B0.y);
                MMA16816(acc[mt][1], a0, a1, a2, a3, B0.z, B0.w);
                MMA16816(acc[mt][2], a0, a1, a2, a3, B1.x, B1.y);
                MMA16816(acc[mt][3], a0, a1, a2, a3, B1.z, B1.w);
            }
        }

        // gates + state update; publish h-half locally and to peer (DSMEM)
#pragma unroll
        for (int mt = 0; mt < 2; mt++) {
#pragma unroll
            for (int jr = 0; jr < 2; jr++) {
                int j = 2 * jr;
                int ci = mt * 4 + j;
                float i0 = sigap(acc[mt][0][j]);
                float i1 = sigap(acc[mt][0][j + 1]);
                float f0 = sigap(acc[mt][1][j]);
                float f1 = sigap(acc[mt][1][j + 1]);
                float g0 = tanhap(acc[mt][2][j]);
                float g1 = tanhap(acc[mt][2][j + 1]);
                float o0 = sigap(acc[mt][3][j]);
                float o1 = sigap(acc[mt][3][j + 1]);
                float c0 = fmaf(f0, c[ci],     i0 * g0);
                float c1 = fmaf(f1, c[ci + 1], i1 * g1);
                c[ci] = c0; c[ci + 1] = c1;
                float h0 = o0 * tanhap(c0);
                float h1 = o1 * tanhap(c1);

                int row = mt * 16 + gid + jr * 8;
                uint32_t off = (uint32_t)((row * ASTRIDE + 32 + ucol) * 2);
                __half2 h2 = __floats2half2_rn(h0, h1);
                *(__half2*)&bufW[row * ASTRIDE + 32 + ucol] = h2;
                uint32_t hv = *reinterpret_cast<uint32_t*>(&h2);
                asm volatile("st.shared::cluster.b32 [%0], %1;"
                             :: "r"(peerW + off), "r"(hv) : "memory");
            }
        }

        // stage x(t+1) (local copy)
        if (t < 255)
            *(__half2*)&bufW[xrow * ASTRIDE + xdp] = __float22half2_rn(xnext);

        CLUSTER_SYNC();   // bufW complete (incl. peer half), bufR free
    }

    // ---- FC: out[b][f] = h_last . W_fc[f][:] + b_fc[f] ----
    // h_256 (full, incl. peer half) lives in buf0 locally.
    float accf[2][4];
#pragma unroll
    for (int mt = 0; mt < 2; mt++)
#pragma unroll
        for (int j = 0; j < 4; j++) accf[mt][j] = 0.0f;

    const uint2* __restrict__ fbase = g_Wfc2 + (s * 16) * 32 + l;
#pragma unroll 2
    for (int kc = 0; kc < 16; kc++) {
        uint2 B = __ldg(fbase + kc * 32);
#pragma unroll
        for (int mt = 0; mt < 2; mt++) {
            uint32_t a0, a1, a2, a3;
            LDMATRIX_X4(a0, a1, a2, a3,
                        aBase[0] + (uint32_t)((mt * 16 * ASTRIDE + 32 + kc * 16) * 2));
            MMA16816(accf[mt], a0, a1, a2, a3, B.x, B.y);
        }
    }

    {
        float2 bf = *(const float2*)&b_fc[ucol];
#pragma unroll
        for (int mt = 0; mt < 2; mt++) {
#pragma unroll
            for (int jr = 0; jr < 2; jr++) {
                int row = b0 + mt * 16 + gid + jr * 8;
                float2 r;
                r.x = accf[mt][2 * jr]     + bf.x;
                r.y = accf[mt][2 * jr + 1] + bf.y;
                *(float2*)&out[(size_t)row * 256 + ucol] = r;
            }
        }
    }
}

extern "C" void kernel_launch(void* const* d_in, const int* in_sizes, int n_in,
                              void* d_out, int out_size) {
    const float* obs  = (const float*)d_in[0];  // [2048,256,32]
    const float* W_ih = (const float*)d_in[1];  // [1024,32]
    const float* W_hh = (const float*)d_in[2];  // [1024,256]
    const float* b_ih = (const float*)d_in[3];  // [1024]
    const float* b_hh = (const float*)d_in[4];  // [1024]
    const float* W_fc = (const float*)d_in[5];  // [256,256]
    const float* b_fc = (const float*)d_in[6];  // [256]
    float* out = (float*)d_out;                 // [2048,256]

    int total = NSLOT * NKC * 2 * 32 + NSLOT * 16 * 32;   // 53248
    prep_kernel<<<(total + 255) / 256, 256>>>(W_ih, W_hh, W_fc);
    lstm_kernel<<<NCTA, 512>>>(obs, b_ih, b_hh, b_fc, out);
}

// round 14
// speedup vs baseline: 2.0539x; 1.0501x over previous
#include <cuda_runtime.h>
#include <cuda_fp16.h>
#include <cstdint>

// LSTM extractor, HMMA m16n8k16 fp16/fp32, cluster-2 N-split.
//   B=2048, T=256, D=32, H=256, F=256.
// 128 CTAs (64 clusters of 2) x 512 threads. Cluster owns M=32 batch rows;
// CTA rank r computes all 4 gates for hidden units [128r, 128r+128).
// R13: mbarrier ping-pong handshake instead of barrier.cluster (no per-step
//      CCTL.IVALL -> weights stay L1-resident; ~150 vs ~490 cyc), and
//      rank-local A layout [x | own-h | peer-h] with per-slot K-permuted
//      weights so kc 0..9 run before the peer wait (peer latency hidden).

#define NKC     18      // K chunks of 16 (K = 288 = 32 x + 256 h)
#define ASTRIDE 296     // halves per A row (592B)
#define NSLOT   32      // 8-unit slots across the cluster
#define NCTA    128

__device__ uint4 g_W2[NSLOT * NKC * 2 * 32];   // per-slot fragment-major
__device__ uint2 g_Wfc2[NSLOT * 16 * 32];

__device__ __forceinline__ float tanhap(float x) {
    float r;
    asm("tanh.approx.f32 %0, %1;" : "=f"(r) : "f"(x));
    return r;
}
__device__ __forceinline__ float sigap(float x) {
    return fmaf(tanhap(0.5f * x), 0.5f, 0.5f);
}

__device__ __forceinline__ uint32_t smemu32(const void* p) {
    uint32_t a;
    asm("{ .reg .u64 t; cvta.to.shared.u64 t, %1; cvt.u32.u64 %0, t; }"
        : "=r"(a) : "l"(p));
    return a;
}
__device__ __forceinline__ uint32_t mapa_u32(uint32_t addr, uint32_t r) {
    uint32_t o;
    asm("mapa.shared::cluster.u32 %0, %1, %2;" : "=r"(o) : "r"(addr), "r"(r));
    return o;
}

#define MBAR_INIT(addr, cnt)                                                \
    asm volatile("mbarrier.init.shared.b64 [%0], %1;"                       \
                 :: "r"(addr), "r"(cnt) : "memory")

// release-arrive on a PEER CTA's mbarrier (cluster scope)
#define MBAR_ARRIVE_PEER(addr)                                              \
    asm volatile("mbarrier.arrive.release.cluster.shared::cluster.b64 _, [%0];" \
                 :: "r"(addr) : "memory")

// acquire parity wait (cluster scope) on LOCAL mbarrier, spin
#define MBAR_WAITP(addr, phase)                                             \
    asm volatile("{\n\t.reg .pred P;\n\t"                                   \
        "WL%=:\n\t"                                                         \
        "mbarrier.try_wait.parity.acquire.cluster.shared::cta.b64 P, [%0], %1;\n\t" \
        "@P bra WD%=;\n\tbra WL%=;\n\tWD%=:\n\t}"                           \
        :: "r"(addr), "r"(phase) : "memory")

#define CLUSTER_SYNC() do {                                                 \
    asm volatile("barrier.cluster.arrive.aligned;" ::: "memory");           \
    asm volatile("barrier.cluster.wait.aligned;" ::: "memory");             \
} while (0)

#define LDMATRIX_X4(a0, a1, a2, a3, addr)                                   \
    asm volatile("ldmatrix.sync.aligned.m8n8.x4.shared.b16 {%0,%1,%2,%3}, [%4];" \
                 : "=r"(a0), "=r"(a1), "=r"(a2), "=r"(a3) : "r"(addr))

#define MMA16816(d, a0, a1, a2, a3, b0, b1)                                 \
    asm volatile("mma.sync.aligned.m16n8k16.row.col.f32.f16.f16.f32 "       \
                 "{%0,%1,%2,%3},{%4,%5,%6,%7},{%8,%9},{%0,%1,%2,%3};"       \
                 : "+f"(d[0]), "+f"(d[1]), "+f"(d[2]), "+f"(d[3])           \
                 : "r"(a0), "r"(a1), "r"(a2), "r"(a3), "r"(b0), "r"(b1))

// ---------------- prep: weights -> per-slot fp16 fragment layouts ---------
__device__ __forceinline__ float wval(const float* W_ih, const float* W_hh,
                                      int col, int k) {
    return (k < 32) ? W_ih[col * 32 + k] : W_hh[col * 256 + (k - 32)];
}
// local K index -> global K index for rank-local A layout [x|own-h|peer-h]
__device__ __forceinline__ int kmap(int rank, int kk) {
    if (kk < 32) return kk;
    int p = kk - 32;
    int gu = (p < 128) ? rank * 128 + p : (rank ^ 1) * 128 + (p - 128);
    return 32 + gu;
}
__device__ __forceinline__ int gumap(int rank, int p) {   // FC h position
    return (p < 128) ? rank * 128 + p : (rank ^ 1) * 128 + (p - 128);
}

__global__ void prep_kernel(const float* __restrict__ W_ih,
                            const float* __restrict__ W_hh,
                            const float* __restrict__ W_fc) {
    int g = blockIdx.x * 256 + threadIdx.x;
    if (g < NSLOT * NKC * 2 * 32) {                 // 36864
        int l = g & 31;
        int t = g >> 5;
        int q = t & 1;  t >>= 1;
        int kc = t % NKC;
        int s  = t / NKC;
        int rank = s >> 4;
        int k0 = kc * 16 + (l & 3) * 2;
        int n  = l >> 2;
        union { __half h[8]; uint4 v; } u;
        for (int hf = 0; hf < 2; hf++) {
            int gate = 2 * q + hf;                  // 0=i 1=f 2=g 3=o
            int col = gate * 256 + s * 8 + n;
            u.h[hf * 4 + 0] = __float2half(wval(W_ih, W_hh, col, kmap(rank, k0)));
            u.h[hf * 4 + 1] = __float2half(wval(W_ih, W_hh, col, kmap(rank, k0 + 1)));
            u.h[hf * 4 + 2] = __float2half(wval(W_ih, W_hh, col, kmap(rank, k0 + 8)));
            u.h[hf * 4 + 3] = __float2half(wval(W_ih, W_hh, col, kmap(rank, k0 + 9)));
        }
        g_W2[g] = u.v;
    } else if (g < NSLOT * NKC * 2 * 32 + NSLOT * 16 * 32) {   // +16384
        int g2 = g - NSLOT * NKC * 2 * 32;
        int l = g2 & 31;
        int t = g2 >> 5;
        int kc = t & 15;
        int s  = t >> 4;
        int rank = s >> 4;
        int k0 = kc * 16 + (l & 3) * 2;
        int n  = l >> 2;
        int col = s * 8 + n;
        union { __half h[4]; uint2 v; } u;
        u.h[0] = __float2half(W_fc[col * 256 + gumap(rank, k0)]);
        u.h[1] = __float2half(W_fc[col * 256 + gumap(rank, k0 + 1)]);
        u.h[2] = __float2half(W_fc[col * 256 + gumap(rank, k0 + 8)]);
        u.h[3] = __float2half(W_fc[col * 256 + gumap(rank, k0 + 9)]);
        g_Wfc2[g2] = u.v;
    }
}

// ---------------- main persistent LSTM + FC kernel ------------------------
__global__ void __launch_bounds__(512, 1) __cluster_dims__(2, 1, 1)
lstm_kernel(const float* __restrict__ obs,
            const float* __restrict__ b_ih,
            const float* __restrict__ b_hh,
            const float* __restrict__ b_fc,
            float* __restrict__ out) {
    __shared__ __align__(16) __half hA[2][32 * ASTRIDE];  // double-buffered A
    __shared__ float bias_s[1024];
    __shared__ __align__(8) unsigned long long mbar[2];

    const int tid  = threadIdx.x;
    const int w    = tid >> 5;
    const int l    = tid & 31;
    const int gid  = l >> 2;
    const int tid4 = l & 3;

    uint32_t rank;
    asm("mov.u32 %0, %%cluster_ctarank;" : "=r"(rank));
    const int s  = (int)rank * 16 + w;     // global 8-unit slot
    const int b0 = (blockIdx.x >> 1) * 32; // cluster's first batch row

    const uint32_t mbarL0 = smemu32(&mbar[0]);
    const uint32_t mbarL1 = smemu32(&mbar[1]);
    const uint32_t mbarP0 = mapa_u32(mbarL0, rank ^ 1u);
    const uint32_t mbarP1 = mapa_u32(mbarL1, rank ^ 1u);
    if (tid == 0) {
        MBAR_INIT(mbarL0, 1);
        MBAR_INIT(mbarL1, 1);
    }

    bias_s[tid]       = b_ih[tid]       + b_hh[tid];
    bias_s[tid + 512] = b_ih[tid + 512] + b_hh[tid + 512];

    // zero buf0 (h regions must start at 0); buf1 fully written in step 0
    for (int i = tid; i < 32 * ASTRIDE; i += 512)
        hA[0][i] = __float2half(0.0f);

    // x staging role: thread -> (row, feature pair)
    const int xrow = tid >> 4;
    const int xdp  = (tid & 15) * 2;
    const float* xptr = obs + (size_t)(b0 + xrow) * 8192 + xdp;
    {   // stage x(0) into buf0
        float2 x2 = *(const float2*)xptr;
        *(__half2*)&hA[0][xrow * ASTRIDE + xdp] = __float22half2_rn(x2);
    }
    __syncthreads();
    CLUSTER_SYNC();   // once: peer mbar init visible before any arrive

    const uint32_t locA0 = smemu32(hA[0]);
    const uint32_t locA1 = smemu32(hA[1]);
    uint32_t peerA[2];
    peerA[0] = mapa_u32(locA0, rank ^ 1u);
    peerA[1] = mapa_u32(locA1, rank ^ 1u);

    float c[8];
#pragma unroll
    for (int i = 0; i < 8; i++) c[i] = 0.0f;

    const uint4* __restrict__ wbase = g_W2 + (s * NKC * 2) * 32 + l;
    const uint32_t aoff = (uint32_t)(((l & 15) * ASTRIDE + (l >> 4) * 8) * 2);
    const uint32_t aBase[2] = { locA0 + aoff, locA1 + aoff };

    float2 bsv[4];
#pragma unroll
    for (int gate = 0; gate < 4; gate++)
        bsv[gate] = *(const float2*)&bias_s[gate * 256 + s * 8 + tid4 * 2];

    const int ownCol  = 32 + w * 8 + tid4 * 2;    // my h cols in MY buffer
    const int peerCol = 160 + w * 8 + tid4 * 2;   // my h cols in PEER buffer
    const int fcCol   = s * 8 + tid4 * 2;         // FC output feature pair

#pragma unroll 1
    for (int t = 0; t < 256; t++) {
        const uint32_t aR = aBase[t & 1];
        const int wb = (t + 1) & 1;
        __half* __restrict__ bufW = hA[wb];
        const uint32_t peerW = peerA[wb];

        // prefetch x(t+1) (overlaps GEMM)
        float2 xnext;
        if (t < 255) xnext = *(const float2*)(xptr + (size_t)(t + 1) * 32);

        float acc[2][4][4];
#pragma unroll
        for (int mt = 0; mt < 2; mt++)
#pragma unroll
            for (int gate = 0; gate < 4; gate++) {
                acc[mt][gate][0] = bsv[gate].x; acc[mt][gate][1] = bsv[gate].y;
                acc[mt][gate][2] = bsv[gate].x; acc[mt][gate][3] = bsv[gate].y;
            }

        // distance-2 software-pipelined weight fetch
        uint4 Bq[2][2];
        Bq[0][0] = __ldg(wbase +  0);
        Bq[0][1] = __ldg(wbase + 32);
        Bq[1][0] = __ldg(wbase + 64);
        Bq[1][1] = __ldg(wbase + 96);

        // --- local portion: kc 0..9 (x + own h, no peer dependency) ---
#pragma unroll
        for (int kc = 0; kc < 10; kc++) {
            const uint4 B0 = Bq[kc & 1][0];
            const uint4 B1 = Bq[kc & 1][1];
            if (kc + 2 < NKC) {
                const uint4* wn = wbase + ((kc + 2) * 2) * 32;
                Bq[kc & 1][0] = __ldg(wn);
                Bq[kc & 1][1] = __ldg(wn + 32);
            }
#pragma unroll
            for (int mt = 0; mt < 2; mt++) {
                uint32_t a0, a1, a2, a3;
                LDMATRIX_X4(a0, a1, a2, a3,
                            aR + (uint32_t)((mt * 16 * ASTRIDE + kc * 16) * 2));
                MMA16816(acc[mt][0], a0, a1, a2, a3, B0.x, B0.y);
                MMA16816(acc[mt][1], a0, a1, a2, a3, B0.z, B0.w);
                MMA16816(acc[mt][2], a0, a1, a2, a3, B1.x, B1.y);
                MMA16816(acc[mt][3], a0, a1, a2, a3, B1.z, B1.w);
            }
        }

        // --- wait for peer's h-half of this step's A buffer ---
        if (t > 0) {
            int phase = ((t - 2 + (t & 1)) >> 1) & 1;
            MBAR_WAITP((t & 1) ? mbarL1 : mbarL0, phase);
        }

        // --- peer portion: kc 10..17 ---
#pragma unroll
        for (int kc = 10; kc < NKC; kc++) {
            const uint4 B0 = Bq[kc & 1][0];
            const uint4 B1 = Bq[kc & 1][1];
            if (kc + 2 < NKC) {
                const uint4* wn = wbase + ((kc + 2) * 2) * 32;
                Bq[kc & 1][0] = __ldg(wn);
                Bq[kc & 1][1] = __ldg(wn + 32);
            }
#pragma unroll
            for (int mt = 0; mt < 2; mt++) {
                uint32_t a0, a1, a2, a3;
                LDMATRIX_X4(a0, a1, a2, a3,
                            aR + (uint32_t)((mt * 16 * ASTRIDE + kc * 16) * 2));
                MMA16816(acc[mt][0], a0, a1, a2, a3, B0.x, B0.y);
                MMA16816(acc[mt][1], a0, a1, a2, a3, B0.z, B0.w);
                MMA16816(acc[mt][2], a0, a1, a2, a3, B1.x, B1.y);
                MMA16816(acc[mt][3], a0, a1, a2, a3, B1.z, B1.w);
            }
        }

        // gates + state update; publish h: own half locally, peer half DSMEM
#pragma unroll
        for (int mt = 0; mt < 2; mt++) {
#pragma unroll
            for (int jr = 0; jr < 2; jr++) {
                int j = 2 * jr;
                int ci = mt * 4 + j;
                float i0 = sigap(acc[mt][0][j]);
                float i1 = sigap(acc[mt][0][j + 1]);
                float f0 = sigap(acc[mt][1][j]);
                float f1 = sigap(acc[mt][1][j + 1]);
                float g0 = tanhap(acc[mt][2][j]);
                float g1 = tanhap(acc[mt][2][j + 1]);
                float o0 = sigap(acc[mt][3][j]);
                float o1 = sigap(acc[mt][3][j + 1]);
                float c0 = fmaf(f0, c[ci],     i0 * g0);
                float c1 = fmaf(f1, c[ci + 1], i1 * g1);
                c[ci] = c0; c[ci + 1] = c1;
                float h0 = o0 * tanhap(c0);
                float h1 = o1 * tanhap(c1);

                int row = mt * 16 + gid + jr * 8;
                __half2 h2 = __floats2half2_rn(h0, h1);
                *(__half2*)&bufW[row * ASTRIDE + ownCol] = h2;
                uint32_t off = (uint32_t)((row * ASTRIDE + peerCol) * 2);
                uint32_t hv = *reinterpret_cast<uint32_t*>(&h2);
                asm volatile("st.shared::cluster.b32 [%0], %1;"
                             :: "r"(peerW + off), "r"(hv) : "memory");
            }
        }

        // stage x(t+1)
        if (t < 255)
            *(__half2*)&bufW[xrow * ASTRIDE + xdp] = __float22half2_rn(xnext);

        __syncthreads();               // all local+DSMEM stores issued/drained
        if (tid == 0)                  // signal peer: buf[wb] peer-half ready,
            MBAR_ARRIVE_PEER(wb ? mbarP1 : mbarP0);  // and my reads of buf[t] done
    }

    // ---- FC: out[b][f] = h_last . W_fc[f][:] + b_fc[f] ----
    // h_256 lives in buf0 (local order [own|peer]); wait peer's final arrive.
    MBAR_WAITP(mbarL0, 1);

    float accf[2][4];
#pragma unroll
    for (int mt = 0; mt < 2; mt++)
#pragma unroll
        for (int j = 0; j < 4; j++) accf[mt][j] = 0.0f;

    const uint2* __restrict__ fbase = g_Wfc2 + (s * 16) * 32 + l;
#pragma unroll 2
    for (int kc = 0; kc < 16; kc++) {
        uint2 B = __ldg(fbase + kc * 32);
#pragma unroll
        for (int mt = 0; mt < 2; mt++) {
            uint32_t a0, a1, a2, a3;
            LDMATRIX_X4(a0, a1, a2, a3,
                        aBase[0] + (uint32_t)((mt * 16 * ASTRIDE + 32 + kc * 16) * 2));
            MMA16816(accf[mt], a0, a1, a2, a3, B.x, B.y);
        }
    }

    {
        float2 bf = *(const float2*)&b_fc[fcCol];
#pragma unroll
        for (int mt = 0; mt < 2; mt++) {
#pragma unroll
            for (int jr = 0; jr < 2; jr++) {
                int row = b0 + mt * 16 + gid + jr * 8;
                float2 r;
                r.x = accf[mt][2 * jr]     + bf.x;
                r.y = accf[mt][2 * jr + 1] + bf.y;
                *(float2*)&out[(size_t)row * 256 + fcCol] = r;
            }
        }
    }

    CLUSTER_SYNC();   // no CTA exits while peer may still touch its smem
}

extern "C" void kernel_launch(void* const* d_in, const int* in_sizes, int n_in,
                              void* d_out, int out_size) {
    const float* obs  = (const float*)d_in[0];  // [2048,256,32]
    const float* W_ih = (const float*)d_in[1];  // [1024,32]
    const float* W_hh = (const float*)d_in[2];  // [1024,256]
    const float* b_ih = (const float*)d_in[3];  // [1024]
    const float* b_hh = (const float*)d_in[4];  // [1024]
    const float* W_fc = (const float*)d_in[5];  // [256,256]
    const float* b_fc = (const float*)d_in[6];  // [256]
    float* out = (float*)d_out;                 // [2048,256]

    int total = NSLOT * NKC * 2 * 32 + NSLOT * 16 * 32;   // 53248
    prep_kernel<<<(total + 255) / 256, 256>>>(W_ih, W_hh, W_fc);
    lstm_kernel<<<NCTA, 512>>>(obs, b_ih, b_hh, b_fc, out);
}

// round 15
// speedup vs baseline: 2.0552x; 1.0006x over previous
#include <cuda_runtime.h>
#include <cuda_fp16.h>
#include <cstdint>

// LSTM extractor, HMMA m16n8k16 fp16/fp32, cluster-2 N-split.
//   B=2048, T=256, D=32, H=256, F=256.
// 128 CTAs (64 clusters of 2) x 512 threads. Cluster owns M=32 batch rows;
// CTA rank r computes all 4 gates for hidden units [128r, 128r+128).
// R14: (a) weight prefetch ring depth 3 (cover L2 ~240cyc),
//      (b) mt-split tail: kc10..17 mt0 first -> acc0 done early; mt0
//          activations/stores overlap the mt1 tail MMAs (B reloads are L1
//          hits), hiding the MUFU burst behind the tensor pipe and shipping
//          the peer h-half earlier.

#define NKC     18      // K chunks of 16 (K = 288 = 32 x + 256 h)
#define ASTRIDE 296     // halves per A row (592B)
#define NSLOT   32      // 8-unit slots across the cluster
#define NCTA    128

__device__ uint4 g_W2[NSLOT * NKC * 2 * 32];   // per-slot fragment-major
__device__ uint2 g_Wfc2[NSLOT * 16 * 32];

__device__ __forceinline__ float tanhap(float x) {
    float r;
    asm("tanh.approx.f32 %0, %1;" : "=f"(r) : "f"(x));
    return r;
}
__device__ __forceinline__ float sigap(float x) {
    return fmaf(tanhap(0.5f * x), 0.5f, 0.5f);
}

__device__ __forceinline__ uint32_t smemu32(const void* p) {
    uint32_t a;
    asm("{ .reg .u64 t; cvta.to.shared.u64 t, %1; cvt.u32.u64 %0, t; }"
        : "=r"(a) : "l"(p));
    return a;
}
__device__ __forceinline__ uint32_t mapa_u32(uint32_t addr, uint32_t r) {
    uint32_t o;
    asm("mapa.shared::cluster.u32 %0, %1, %2;" : "=r"(o) : "r"(addr), "r"(r));
    return o;
}

#define MBAR_INIT(addr, cnt)                                                \
    asm volatile("mbarrier.init.shared.b64 [%0], %1;"                       \
                 :: "r"(addr), "r"(cnt) : "memory")

#define MBAR_ARRIVE_PEER(addr)                                              \
    asm volatile("mbarrier.arrive.release.cluster.shared::cluster.b64 _, [%0];" \
                 :: "r"(addr) : "memory")

#define MBAR_WAITP(addr, phase)                                             \
    asm volatile("{\n\t.reg .pred P;\n\t"                                   \
        "WL%=:\n\t"                                                         \
        "mbarrier.try_wait.parity.acquire.cluster.shared::cta.b64 P, [%0], %1;\n\t" \
        "@P bra WD%=;\n\tbra WL%=;\n\tWD%=:\n\t}"                           \
        :: "r"(addr), "r"(phase) : "memory")

#define CLUSTER_SYNC() do {                                                 \
    asm volatile("barrier.cluster.arrive.aligned;" ::: "memory");           \
    asm volatile("barrier.cluster.wait.aligned;" ::: "memory");             \
} while (0)

#define LDMATRIX_X4(a0, a1, a2, a3, addr)                                   \
    asm volatile("ldmatrix.sync.aligned.m8n8.x4.shared.b16 {%0,%1,%2,%3}, [%4];" \
                 : "=r"(a0), "=r"(a1), "=r"(a2), "=r"(a3) : "r"(addr))

#define MMA16816(d, a0, a1, a2, a3, b0, b1)                                 \
    asm volatile("mma.sync.aligned.m16n8k16.row.col.f32.f16.f16.f32 "       \
                 "{%0,%1,%2,%3},{%4,%5,%6,%7},{%8,%9},{%0,%1,%2,%3};"       \
                 : "+f"(d[0]), "+f"(d[1]), "+f"(d[2]), "+f"(d[3])           \
                 : "r"(a0), "r"(a1), "r"(a2), "r"(a3), "r"(b0), "r"(b1))

// ---------------- prep: weights -> per-slot fp16 fragment layouts ---------
__device__ __forceinline__ float wval(const float* W_ih, const float* W_hh,
                                      int col, int k) {
    return (k < 32) ? W_ih[col * 32 + k] : W_hh[col * 256 + (k - 32)];
}
// local K index -> global K index for rank-local A layout [x|own-h|peer-h]
__device__ __forceinline__ int kmap(int rank, int kk) {
    if (kk < 32) return kk;
    int p = kk - 32;
    int gu = (p < 128) ? rank * 128 + p : (rank ^ 1) * 128 + (p - 128);
    return 32 + gu;
}
__device__ __forceinline__ int gumap(int rank, int p) {   // FC h position
    return (p < 128) ? rank * 128 + p : (rank ^ 1) * 128 + (p - 128);
}

__global__ void prep_kernel(const float* __restrict__ W_ih,
                            const float* __restrict__ W_hh,
                            const float* __restrict__ W_fc) {
    int g = blockIdx.x * 256 + threadIdx.x;
    if (g < NSLOT * NKC * 2 * 32) {                 // 36864
        int l = g & 31;
        int t = g >> 5;
        int q = t & 1;  t >>= 1;
        int kc = t % NKC;
        int s  = t / NKC;
        int rank = s >> 4;
        int k0 = kc * 16 + (l & 3) * 2;
        int n  = l >> 2;
        union { __half h[8]; uint4 v; } u;
        for (int hf = 0; hf < 2; hf++) {
            int gate = 2 * q + hf;                  // 0=i 1=f 2=g 3=o
            int col = gate * 256 + s * 8 + n;
            u.h[hf * 4 + 0] = __float2half(wval(W_ih, W_hh, col, kmap(rank, k0)));
            u.h[hf * 4 + 1] = __float2half(wval(W_ih, W_hh, col, kmap(rank, k0 + 1)));
            u.h[hf * 4 + 2] = __float2half(wval(W_ih, W_hh, col, kmap(rank, k0 + 8)));
            u.h[hf * 4 + 3] = __float2half(wval(W_ih, W_hh, col, kmap(rank, k0 + 9)));
        }
        g_W2[g] = u.v;
    } else if (g < NSLOT * NKC * 2 * 32 + NSLOT * 16 * 32) {   // +16384
        int g2 = g - NSLOT * NKC * 2 * 32;
        int l = g2 & 31;
        int t = g2 >> 5;
        int kc = t & 15;
        int s  = t >> 4;
        int rank = s >> 4;
        int k0 = kc * 16 + (l & 3) * 2;
        int n  = l >> 2;
        int col = s * 8 + n;
        union { __half h[4]; uint2 v; } u;
        u.h[0] = __float2half(W_fc[col * 256 + gumap(rank, k0)]);
        u.h[1] = __float2half(W_fc[col * 256 + gumap(rank, k0 + 1)]);
        u.h[2] = __float2half(W_fc[col * 256 + gumap(rank, k0 + 8)]);
        u.h[3] = __float2half(W_fc[col * 256 + gumap(rank, k0 + 9)]);
        g_Wfc2[g2] = u.v;
    }
}

// activation + h store for one mt tile (used twice per step)
#define ACT_STORE(ACC, CBASE, MT)                                           \
    do {                                                                    \
        _Pragma("unroll")                                                   \
        for (int jr = 0; jr < 2; jr++) {                                    \
            int j = 2 * jr;                                                 \
            float i0 = sigap(ACC[0][j]);                                    \
            float i1 = sigap(ACC[0][j + 1]);                                \
            float f0 = sigap(ACC[1][j]);                                    \
            float f1 = sigap(ACC[1][j + 1]);                                \
            float g0 = tanhap(ACC[2][j]);                                   \
            float g1 = tanhap(ACC[2][j + 1]);                               \
            float o0 = sigap(ACC[3][j]);                                    \
            float o1 = sigap(ACC[3][j + 1]);                                \
            float c0 = fmaf(f0, CBASE[j],     i0 * g0);                     \
            float c1 = fmaf(f1, CBASE[j + 1], i1 * g1);                     \
            CBASE[j] = c0; CBASE[j + 1] = c1;                               \
            float h0 = o0 * tanhap(c0);                                     \
            float h1 = o1 * tanhap(c1);                                     \
            int row = (MT) * 16 + gid + jr * 8;                             \
            __half2 h2 = __floats2half2_rn(h0, h1);                         \
            *(__half2*)&bufW[row * ASTRIDE + ownCol] = h2;                  \
            uint32_t off = (uint32_t)((row * ASTRIDE + peerCol) * 2);       \
            uint32_t hv = *reinterpret_cast<uint32_t*>(&h2);                \
            asm volatile("st.shared::cluster.b32 [%0], %1;"                 \
                         :: "r"(peerW + off), "r"(hv) : "memory");          \
        }                                                                   \
    } while (0)

// ---------------- main persistent LSTM + FC kernel ------------------------
__global__ void __launch_bounds__(512, 1) __cluster_dims__(2, 1, 1)
lstm_kernel(const float* __restrict__ obs,
            const float* __restrict__ b_ih,
            const float* __restrict__ b_hh,
            const float* __restrict__ b_fc,
            float* __restrict__ out) {
    __shared__ __align__(16) __half hA[2][32 * ASTRIDE];  // double-buffered A
    __shared__ float bias_s[1024];
    __shared__ __align__(8) unsigned long long mbar[2];

    const int tid  = threadIdx.x;
    const int w    = tid >> 5;
    const int l    = tid & 31;
    const int gid  = l >> 2;
    const int tid4 = l & 3;

    uint32_t rank;
    asm("mov.u32 %0, %%cluster_ctarank;" : "=r"(rank));
    const int s  = (int)rank * 16 + w;     // global 8-unit slot
    const int b0 = (blockIdx.x >> 1) * 32; // cluster's first batch row

    const uint32_t mbarL0 = smemu32(&mbar[0]);
    const uint32_t mbarL1 = smemu32(&mbar[1]);
    const uint32_t mbarP0 = mapa_u32(mbarL0, rank ^ 1u);
    const uint32_t mbarP1 = mapa_u32(mbarL1, rank ^ 1u);
    if (tid == 0) {
        MBAR_INIT(mbarL0, 1);
        MBAR_INIT(mbarL1, 1);
    }

    bias_s[tid]       = b_ih[tid]       + b_hh[tid];
    bias_s[tid + 512] = b_ih[tid + 512] + b_hh[tid + 512];

    // zero buf0 (h regions must start at 0); buf1 fully written in step 0
    for (int i = tid; i < 32 * ASTRIDE; i += 512)
        hA[0][i] = __float2half(0.0f);

    // x staging role: thread -> (row, feature pair)
    const int xrow = tid >> 4;
    const int xdp  = (tid & 15) * 2;
    const float* xptr = obs + (size_t)(b0 + xrow) * 8192 + xdp;
    {   // stage x(0) into buf0
        float2 x2 = *(const float2*)xptr;
        *(__half2*)&hA[0][xrow * ASTRIDE + xdp] = __float22half2_rn(x2);
    }
    __syncthreads();
    CLUSTER_SYNC();   // once: peer mbar init visible before any arrive

    const uint32_t locA0 = smemu32(hA[0]);
    const uint32_t locA1 = smemu32(hA[1]);
    uint32_t peerA[2];
    peerA[0] = mapa_u32(locA0, rank ^ 1u);
    peerA[1] = mapa_u32(locA1, rank ^ 1u);

    float c[8];
#pragma unroll
    for (int i = 0; i < 8; i++) c[i] = 0.0f;

    const uint4* __restrict__ wbase = g_W2 + (s * NKC * 2) * 32 + l;
    const uint32_t aoff = (uint32_t)(((l & 15) * ASTRIDE + (l >> 4) * 8) * 2);
    const uint32_t aBase[2] = { locA0 + aoff, locA1 + aoff };

    float2 bsv[4];
#pragma unroll
    for (int gate = 0; gate < 4; gate++)
        bsv[gate] = *(const float2*)&bias_s[gate * 256 + s * 8 + tid4 * 2];

    const int ownCol  = 32 + w * 8 + tid4 * 2;    // my h cols in MY buffer
    const int peerCol = 160 + w * 8 + tid4 * 2;   // my h cols in PEER buffer
    const int fcCol   = s * 8 + tid4 * 2;         // FC output feature pair

#pragma unroll 1
    for (int t = 0; t < 256; t++) {
        const uint32_t aR = aBase[t & 1];
        const int wb = (t + 1) & 1;
        __half* __restrict__ bufW = hA[wb];
        const uint32_t peerW = peerA[wb];

        // prefetch x(t+1) (overlaps GEMM)
        float2 xnext;
        if (t < 255) xnext = *(const float2*)(xptr + (size_t)(t + 1) * 32);

        float acc0[4][4], acc1[4][4];
#pragma unroll
        for (int gate = 0; gate < 4; gate++) {
            acc0[gate][0] = bsv[gate].x; acc0[gate][1] = bsv[gate].y;
            acc0[gate][2] = bsv[gate].x; acc0[gate][3] = bsv[gate].y;
            acc1[gate][0] = bsv[gate].x; acc1[gate][1] = bsv[gate].y;
            acc1[gate][2] = bsv[gate].x; acc1[gate][3] = bsv[gate].y;
        }

        // depth-3 weight prefetch ring
        uint4 R[3][2];
#pragma unroll
        for (int q = 0; q < 3; q++) {
            R[q][0] = __ldg(wbase + (q * 2    ) * 32);
            R[q][1] = __ldg(wbase + (q * 2 + 1) * 32);
        }

        // --- local K: kc 0..9 (x + own h), both mt ---
#pragma unroll
        for (int kc = 0; kc < 10; kc++) {
            const uint4 B0 = R[kc % 3][0];
            const uint4 B1 = R[kc % 3][1];
            if (kc + 3 < NKC) {
                const uint4* wn = wbase + ((kc + 3) * 2) * 32;
                R[kc % 3][0] = __ldg(wn);
                R[kc % 3][1] = __ldg(wn + 32);
            }
            uint32_t a0, a1, a2, a3;
            LDMATRIX_X4(a0, a1, a2, a3,
                        aR + (uint32_t)((kc * 16) * 2));
            MMA16816(acc0[0], a0, a1, a2, a3, B0.x, B0.y);
            MMA16816(acc0[1], a0, a1, a2, a3, B0.z, B0.w);
            MMA16816(acc0[2], a0, a1, a2, a3, B1.x, B1.y);
            MMA16816(acc0[3], a0, a1, a2, a3, B1.z, B1.w);
            LDMATRIX_X4(a0, a1, a2, a3,
                        aR + (uint32_t)((16 * ASTRIDE + kc * 16) * 2));
            MMA16816(acc1[0], a0, a1, a2, a3, B0.x, B0.y);
            MMA16816(acc1[1], a0, a1, a2, a3, B0.z, B0.w);
            MMA16816(acc1[2], a0, a1, a2, a3, B1.x, B1.y);
            MMA16816(acc1[3], a0, a1, a2, a3, B1.z, B1.w);
        }

        // --- wait for peer's h-half of this step's A buffer ---
        if (t > 0) {
            int phase = ((t - 2 + (t & 1)) >> 1) & 1;
            MBAR_WAITP((t & 1) ? mbarL1 : mbarL0, phase);
        }

        // --- peer K, mt0 only: kc 10..17 -> acc0 completes early ---
#pragma unroll
        for (int kc = 10; kc < NKC; kc++) {
            const uint4 B0 = R[kc % 3][0];
            const uint4 B1 = R[kc % 3][1];
            if (kc + 3 < NKC) {
                const uint4* wn = wbase + ((kc + 3) * 2) * 32;
                R[kc % 3][0] = __ldg(wn);
                R[kc % 3][1] = __ldg(wn + 32);
            }
            uint32_t a0, a1, a2, a3;
            LDMATRIX_X4(a0, a1, a2, a3,
                        aR + (uint32_t)((kc * 16) * 2));
            MMA16816(acc0[0], a0, a1, a2, a3, B0.x, B0.y);
            MMA16816(acc0[1], a0, a1, a2, a3, B0.z, B0.w);
            MMA16816(acc0[2], a0, a1, a2, a3, B1.x, B1.y);
            MMA16816(acc0[3], a0, a1, a2, a3, B1.z, B1.w);
        }

        // --- mt0 activations (MUFU) overlap mt1 tail MMAs below ---
        ACT_STORE(acc0, (c + 0), 0);

        // --- peer K, mt1: kc 10..17 (B reloads are L1 hits) ---
        {
            uint4 S[2][2];
            S[0][0] = __ldg(wbase + (10 * 2    ) * 32);
            S[0][1] = __ldg(wbase + (10 * 2 + 1) * 32);
            S[1][0] = __ldg(wbase + (11 * 2    ) * 32);
            S[1][1] = __ldg(wbase + (11 * 2 + 1) * 32);
#pragma unroll
            for (int kc = 10; kc < NKC; kc++) {
                const uint4 B0 = S[kc & 1][0];
                const uint4 B1 = S[kc & 1][1];
                if (kc + 2 < NKC) {
                    const uint4* wn = wbase + ((kc + 2) * 2) * 32;
                    S[kc & 1][0] = __ldg(wn);
                    S[kc & 1][1] = __ldg(wn + 32);
                }
                uint32_t a0, a1, a2, a3;
                LDMATRIX_X4(a0, a1, a2, a3,
                            aR + (uint32_t)((16 * ASTRIDE + kc * 16) * 2));
                MMA16816(acc1[0], a0, a1, a2, a3, B0.x, B0.y);
                MMA16816(acc1[1], a0, a1, a2, a3, B0.z, B0.w);
                MMA16816(acc1[2], a0, a1, a2, a3, B1.x, B1.y);
                MMA16816(acc1[3], a0, a1, a2, a3, B1.z, B1.w);
            }
        }

        ACT_STORE(acc1, (c + 4), 1);

        // stage x(t+1)
        if (t < 255)
            *(__half2*)&bufW[xrow * ASTRIDE + xdp] = __float22half2_rn(xnext);

        __syncthreads();               // all local+DSMEM stores drained
        if (tid == 0)                  // signal peer: buf[wb] peer-half ready,
            MBAR_ARRIVE_PEER(wb ? mbarP1 : mbarP0);  // my reads of buf[t] done
    }

    // ---- FC: out[b][f] = h_last . W_fc[f][:] + b_fc[f] ----
    // h_256 lives in buf0 (local order [own|peer]); wait peer's final arrive.
    MBAR_WAITP(mbarL0, 1);

    float accf[2][4];
#pragma unroll
    for (int mt = 0; mt < 2; mt++)
#pragma unroll
        for (int j = 0; j < 4; j++) accf[mt][j] = 0.0f;

    const uint2* __restrict__ fbase = g_Wfc2 + (s * 16) * 32 + l;
#pragma unroll 2
    for (int kc = 0; kc < 16; kc++) {
        uint2 B = __ldg(fbase + kc * 32);
#pragma unroll
        for (int mt = 0; mt < 2; mt++) {
            uint32_t a0, a1, a2, a3;
            LDMATRIX_X4(a0, a1, a2, a3,
                        aBase[0] + (uint32_t)((mt * 16 * ASTRIDE + 32 + kc * 16) * 2));
            MMA16816(accf[mt], a0, a1, a2, a3, B.x, B.y);
        }
    }

    {
        float2 bf = *(const float2*)&b_fc[fcCol];
#pragma unroll
        for (int mt = 0; mt < 2; mt++) {
#pragma unroll
            for (int jr = 0; jr < 2; jr++) {
                int row = b0 + mt * 16 + gid + jr * 8;
                float2 r;
                r.x = accf[mt][2 * jr]     + bf.x;
                r.y = accf[mt][2 * jr + 1] + bf.y;
                *(float2*)&out[(size_t)row * 256 + fcCol] = r;
            }
        }
    }

    CLUSTER_SYNC();   // no CTA exits while peer may still touch its smem
}

extern "C" void kernel_launch(void* const* d_in, const int* in_sizes, int n_in,
                              void* d_out, int out_size) {
    const float* obs  = (const float*)d_in[0];  // [2048,256,32]
    const float* W_ih = (const float*)d_in[1];  // [1024,32]
    const float* W_hh = (const float*)d_in[2];  // [1024,256]
    const float* b_ih = (const float*)d_in[3];  // [1024]
    const float* b_hh = (const float*)d_in[4];  // [1024]
    const float* W_fc = (const float*)d_in[5];  // [256,256]
    const float* b_fc = (const float*)d_in[6];  // [256]
    float* out = (float*)d_out;                 // [2048,256]

    int total = NSLOT * NKC * 2 * 32 + NSLOT * 16 * 32;   // 53248
    prep_kernel<<<(total + 255) / 256, 256>>>(W_ih, W_hh, W_fc);
    lstm_kernel<<<NCTA, 512>>>(obs, b_ih, b_hh, b_fc, out);
}

// round 16
// speedup vs baseline: 2.1076x; 1.0255x over previous
#include <cuda_runtime.h>
#include <cuda_fp16.h>
#include <cstdint>

// LSTM extractor, HMMA m16n8k16 fp16/fp32, cluster-2 N-split.
//   B=2048, T=256, D=32, H=256, F=256.
// 128 CTAs (64 clusters of 2) x 512 threads. Cluster owns M=32 batch rows;
// CTA rank r computes all 4 gates for hidden units [128r, 128r+128).
// R15: weights for kc 0..9 are SMEM-RESIDENT (160KB loaded once; LDS.128
//      conflict-free, zero L2, 29cyc) -> only kc 10..17 stream from L2, and
//      their depth-3 ring is issued at STEP START (~800cyc of cover).
//      Unified tail (mt-split reverted).

#define NKC     18      // K chunks of 16 (K = 288 = 32 x + 256 h)
#define NRES    10      // resident K chunks (x + own h)
#define ASTRIDE 296     // halves per A row (592B)
#define NSLOT   32      // 8-unit slots across the cluster
#define NCTA    128

__device__ uint4 g_W2[NSLOT * NKC * 2 * 32];   // per-slot fragment-major
__device__ uint2 g_Wfc2[NSLOT * 16 * 32];

struct SmemLayout {
    __half hA[2][32 * ASTRIDE];                // 37,888 B (double-buffered A)
    float bias[1024];                          //  4,096 B
    unsigned long long mbar[2];                //     16 B
    uint4 wres[16][NRES][2][32];               // 163,840 B resident weights
};
#define SMEM_TOTAL ((int)sizeof(SmemLayout))   // 205,840 B

__device__ __forceinline__ float tanhap(float x) {
    float r;
    asm("tanh.approx.f32 %0, %1;" : "=f"(r) : "f"(x));
    return r;
}
__device__ __forceinline__ float sigap(float x) {
    return fmaf(tanhap(0.5f * x), 0.5f, 0.5f);
}

__device__ __forceinline__ uint32_t smemu32(const void* p) {
    uint32_t a;
    asm("{ .reg .u64 t; cvta.to.shared.u64 t, %1; cvt.u32.u64 %0, t; }"
        : "=r"(a) : "l"(p));
    return a;
}
__device__ __forceinline__ uint32_t mapa_u32(uint32_t addr, uint32_t r) {
    uint32_t o;
    asm("mapa.shared::cluster.u32 %0, %1, %2;" : "=r"(o) : "r"(addr), "r"(r));
    return o;
}

#define MBAR_INIT(addr, cnt)                                                \
    asm volatile("mbarrier.init.shared.b64 [%0], %1;"                       \
                 :: "r"(addr), "r"(cnt) : "memory")

#define MBAR_ARRIVE_PEER(addr)                                              \
    asm volatile("mbarrier.arrive.release.cluster.shared::cluster.b64 _, [%0];" \
                 :: "r"(addr) : "memory")

#define MBAR_WAITP(addr, phase)                                             \
    asm volatile("{\n\t.reg .pred P;\n\t"                                   \
        "WL%=:\n\t"                                                         \
        "mbarrier.try_wait.parity.acquire.cluster.shared::cta.b64 P, [%0], %1;\n\t" \
        "@P bra WD%=;\n\tbra WL%=;\n\tWD%=:\n\t}"                           \
        :: "r"(addr), "r"(phase) : "memory")

#define CLUSTER_SYNC() do {                                                 \
    asm volatile("barrier.cluster.arrive.aligned;" ::: "memory");           \
    asm volatile("barrier.cluster.wait.aligned;" ::: "memory");             \
} while (0)

#define LDMATRIX_X4(a0, a1, a2, a3, addr)                                   \
    asm volatile("ldmatrix.sync.aligned.m8n8.x4.shared.b16 {%0,%1,%2,%3}, [%4];" \
                 : "=r"(a0), "=r"(a1), "=r"(a2), "=r"(a3) : "r"(addr))

#define MMA16816(d, a0, a1, a2, a3, b0, b1)                                 \
    asm volatile("mma.sync.aligned.m16n8k16.row.col.f32.f16.f16.f32 "       \
                 "{%0,%1,%2,%3},{%4,%5,%6,%7},{%8,%9},{%0,%1,%2,%3};"       \
                 : "+f"(d[0]), "+f"(d[1]), "+f"(d[2]), "+f"(d[3])           \
                 : "r"(a0), "r"(a1), "r"(a2), "r"(a3), "r"(b0), "r"(b1))

// ---------------- prep: weights -> per-slot fp16 fragment layouts ---------
__device__ __forceinline__ float wval(const float* W_ih, const float* W_hh,
                                      int col, int k) {
    return (k < 32) ? W_ih[col * 32 + k] : W_hh[col * 256 + (k - 32)];
}
// local K index -> global K index for rank-local A layout [x|own-h|peer-h]
__device__ __forceinline__ int kmap(int rank, int kk) {
    if (kk < 32) return kk;
    int p = kk - 32;
    int gu = (p < 128) ? rank * 128 + p : (rank ^ 1) * 128 + (p - 128);
    return 32 + gu;
}
__device__ __forceinline__ int gumap(int rank, int p) {   // FC h position
    return (p < 128) ? rank * 128 + p : (rank ^ 1) * 128 + (p - 128);
}

__global__ void prep_kernel(const float* __restrict__ W_ih,
                            const float* __restrict__ W_hh,
                            const float* __restrict__ W_fc) {
    int g = blockIdx.x * 256 + threadIdx.x;
    if (g < NSLOT * NKC * 2 * 32) {                 // 36864
        int l = g & 31;
        int t = g >> 5;
        int q = t & 1;  t >>= 1;
        int kc = t % NKC;
        int s  = t / NKC;
        int rank = s >> 4;
        int k0 = kc * 16 + (l & 3) * 2;
        int n  = l >> 2;
        union { __half h[8]; uint4 v; } u;
        for (int hf = 0; hf < 2; hf++) {
            int gate = 2 * q + hf;                  // 0=i 1=f 2=g 3=o
            int col = gate * 256 + s * 8 + n;
            u.h[hf * 4 + 0] = __float2half(wval(W_ih, W_hh, col, kmap(rank, k0)));
            u.h[hf * 4 + 1] = __float2half(wval(W_ih, W_hh, col, kmap(rank, k0 + 1)));
            u.h[hf * 4 + 2] = __float2half(wval(W_ih, W_hh, col, kmap(rank, k0 + 8)));
            u.h[hf * 4 + 3] = __float2half(wval(W_ih, W_hh, col, kmap(rank, k0 + 9)));
        }
        g_W2[g] = u.v;
    } else if (g < NSLOT * NKC * 2 * 32 + NSLOT * 16 * 32) {   // +16384
        int g2 = g - NSLOT * NKC * 2 * 32;
        int l = g2 & 31;
        int t = g2 >> 5;
        int kc = t & 15;
        int s  = t >> 4;
        int rank = s >> 4;
        int k0 = kc * 16 + (l & 3) * 2;
        int n  = l >> 2;
        int col = s * 8 + n;
        union { __half h[4]; uint2 v; } u;
        u.h[0] = __float2half(W_fc[col * 256 + gumap(rank, k0)]);
        u.h[1] = __float2half(W_fc[col * 256 + gumap(rank, k0 + 1)]);
        u.h[2] = __float2half(W_fc[col * 256 + gumap(rank, k0 + 8)]);
        u.h[3] = __float2half(W_fc[col * 256 + gumap(rank, k0 + 9)]);
        g_Wfc2[g2] = u.v;
    }
}

// ---------------- main persistent LSTM + FC kernel ------------------------
__global__ void __launch_bounds__(512, 1) __cluster_dims__(2, 1, 1)
lstm_kernel(const float* __restrict__ obs,
            const float* __restrict__ b_ih,
            const float* __restrict__ b_hh,
            const float* __restrict__ b_fc,
            float* __restrict__ out) {
    extern __shared__ __align__(16) char smem_raw[];
    SmemLayout& S = *reinterpret_cast<SmemLayout*>(smem_raw);

    const int tid  = threadIdx.x;
    const int w    = tid >> 5;
    const int l    = tid & 31;
    const int gid  = l >> 2;
    const int tid4 = l & 3;

    uint32_t rank;
    asm("mov.u32 %0, %%cluster_ctarank;" : "=r"(rank));
    const int s  = (int)rank * 16 + w;     // global 8-unit slot
    const int b0 = (blockIdx.x >> 1) * 32; // cluster's first batch row

    const uint32_t mbarL0 = smemu32(&S.mbar[0]);
    const uint32_t mbarL1 = smemu32(&S.mbar[1]);
    const uint32_t mbarP0 = mapa_u32(mbarL0, rank ^ 1u);
    const uint32_t mbarP1 = mapa_u32(mbarL1, rank ^ 1u);
    if (tid == 0) {
        MBAR_INIT(mbarL0, 1);
        MBAR_INIT(mbarL1, 1);
    }

    S.bias[tid]       = b_ih[tid]       + b_hh[tid];
    S.bias[tid + 512] = b_ih[tid + 512] + b_hh[tid + 512];

    // zero buf0 (h regions must start at 0); buf1 fully written in step 0
    for (int i = tid; i < 32 * ASTRIDE; i += 512)
        S.hA[0][i] = __float2half(0.0f);

    const uint4* __restrict__ wbase = g_W2 + (s * NKC * 2) * 32 + l;

    // load my resident weight slice (kc 0..9). Writer == reader thread, so
    // no barrier needed for these.
#pragma unroll
    for (int kc = 0; kc < NRES; kc++) {
        S.wres[w][kc][0][l] = __ldg(wbase + (kc * 2    ) * 32);
        S.wres[w][kc][1][l] = __ldg(wbase + (kc * 2 + 1) * 32);
    }

    // x staging role: thread -> (row, feature pair)
    const int xrow = tid >> 4;
    const int xdp  = (tid & 15) * 2;
    const float* xptr = obs + (size_t)(b0 + xrow) * 8192 + xdp;
    {   // stage x(0) into buf0
        float2 x2 = *(const float2*)xptr;
        *(__half2*)&S.hA[0][xrow * ASTRIDE + xdp] = __float22half2_rn(x2);
    }
    __syncthreads();
    CLUSTER_SYNC();   // once: peer mbar init visible before any arrive

    const uint32_t locA0 = smemu32(S.hA[0]);
    const uint32_t locA1 = smemu32(S.hA[1]);
    uint32_t peerA[2];
    peerA[0] = mapa_u32(locA0, rank ^ 1u);
    peerA[1] = mapa_u32(locA1, rank ^ 1u);

    float c[8];
#pragma unroll
    for (int i = 0; i < 8; i++) c[i] = 0.0f;

    const uint32_t aoff = (uint32_t)(((l & 15) * ASTRIDE + (l >> 4) * 8) * 2);
    const uint32_t aBase[2] = { locA0 + aoff, locA1 + aoff };

    float2 bsv[4];
#pragma unroll
    for (int gate = 0; gate < 4; gate++)
        bsv[gate] = *(const float2*)&S.bias[gate * 256 + s * 8 + tid4 * 2];

    const int ownCol  = 32 + w * 8 + tid4 * 2;    // my h cols in MY buffer
    const int peerCol = 160 + w * 8 + tid4 * 2;   // my h cols in PEER buffer
    const int fcCol   = s * 8 + tid4 * 2;         // FC output feature pair

    const uint4* __restrict__ wres = &S.wres[w][0][0][l];   // stride 32 per q

#pragma unroll 1
    for (int t = 0; t < 256; t++) {
        const uint32_t aR = aBase[t & 1];
        const int wb = (t + 1) & 1;
        __half* __restrict__ bufW = S.hA[wb];
        const uint32_t peerW = peerA[wb];

        // issue streamed-weight ring (kc 10..12) NOW: covered by the whole
        // resident phase (~800 cyc) before first consumption.
        uint4 R[3][2];
#pragma unroll
        for (int q = 0; q < 3; q++) {
            R[q][0] = __ldg(wbase + ((10 + q) * 2    ) * 32);
            R[q][1] = __ldg(wbase + ((10 + q) * 2 + 1) * 32);
        }

        // prefetch x(t+1) (overlaps GEMM)
        float2 xnext;
        if (t < 255) xnext = *(const float2*)(xptr + (size_t)(t + 1) * 32);

        float acc0[4][4], acc1[4][4];
#pragma unroll
        for (int gate = 0; gate < 4; gate++) {
            acc0[gate][0] = bsv[gate].x; acc0[gate][1] = bsv[gate].y;
            acc0[gate][2] = bsv[gate].x; acc0[gate][3] = bsv[gate].y;
            acc1[gate][0] = bsv[gate].x; acc1[gate][1] = bsv[gate].y;
            acc1[gate][2] = bsv[gate].x; acc1[gate][3] = bsv[gate].y;
        }

        // --- resident K: kc 0..9 (x + own h), both mt; B via LDS.128 ---
#pragma unroll
        for (int kc = 0; kc < NRES; kc++) {
            const uint4 B0 = wres[(kc * 2    ) * 32];
            const uint4 B1 = wres[(kc * 2 + 1) * 32];
            uint32_t a0, a1, a2, a3;
            LDMATRIX_X4(a0, a1, a2, a3,
                        aR + (uint32_t)((kc * 16) * 2));
            MMA16816(acc0[0], a0, a1, a2, a3, B0.x, B0.y);
            MMA16816(acc0[1], a0, a1, a2, a3, B0.z, B0.w);
            MMA16816(acc0[2], a0, a1, a2, a3, B1.x, B1.y);
            MMA16816(acc0[3], a0, a1, a2, a3, B1.z, B1.w);
            LDMATRIX_X4(a0, a1, a2, a3,
                        aR + (uint32_t)((16 * ASTRIDE + kc * 16) * 2));
            MMA16816(acc1[0], a0, a1, a2, a3, B0.x, B0.y);
            MMA16816(acc1[1], a0, a1, a2, a3, B0.z, B0.w);
            MMA16816(acc1[2], a0, a1, a2, a3, B1.x, B1.y);
            MMA16816(acc1[3], a0, a1, a2, a3, B1.z, B1.w);
        }

        // --- wait for peer's h-half of this step's A buffer ---
        if (t > 0) {
            int phase = ((t - 2 + (t & 1)) >> 1) & 1;
            MBAR_WAITP((t & 1) ? mbarL1 : mbarL0, phase);
        }

        // --- streamed K: kc 10..17 (peer h), both mt; ring depth 3 ---
#pragma unroll
        for (int kc = 10; kc < NKC; kc++) {
            const uint4 B0 = R[(kc - 10) % 3][0];
            const uint4 B1 = R[(kc - 10) % 3][1];
            if (kc + 3 < NKC) {
                const uint4* wn = wbase + ((kc + 3) * 2) * 32;
                R[(kc - 10) % 3][0] = __ldg(wn);
                R[(kc - 10) % 3][1] = __ldg(wn + 32);
            }
            uint32_t a0, a1, a2, a3;
            LDMATRIX_X4(a0, a1, a2, a3,
                        aR + (uint32_t)((kc * 16) * 2));
            MMA16816(acc0[0], a0, a1, a2, a3, B0.x, B0.y);
            MMA16816(acc0[1], a0, a1, a2, a3, B0.z, B0.w);
            MMA16816(acc0[2], a0, a1, a2, a3, B1.x, B1.y);
            MMA16816(acc0[3], a0, a1, a2, a3, B1.z, B1.w);
            LDMATRIX_X4(a0, a1, a2, a3,
                        aR + (uint32_t)((16 * ASTRIDE + kc * 16) * 2));
            MMA16816(acc1[0], a0, a1, a2, a3, B0.x, B0.y);
            MMA16816(acc1[1], a0, a1, a2, a3, B0.z, B0.w);
            MMA16816(acc1[2], a0, a1, a2, a3, B1.x, B1.y);
            MMA16816(acc1[3], a0, a1, a2, a3, B1.z, B1.w);
        }

        // gates + state update; publish h: own half locally, peer half DSMEM
#pragma unroll
        for (int mt = 0; mt < 2; mt++) {
            float* acc = mt ? &acc1[0][0] : &acc0[0][0];
            float* cb  = c + mt * 4;
#pragma unroll
            for (int jr = 0; jr < 2; jr++) {
                int j = 2 * jr;
                float i0 = sigap(acc[0 * 4 + j]);
                float i1 = sigap(acc[0 * 4 + j + 1]);
                float f0 = sigap(acc[1 * 4 + j]);
                float f1 = sigap(acc[1 * 4 + j + 1]);
                float g0 = tanhap(acc[2 * 4 + j]);
                float g1 = tanhap(acc[2 * 4 + j + 1]);
                float o0 = sigap(acc[3 * 4 + j]);
                float o1 = sigap(acc[3 * 4 + j + 1]);
                float c0 = fmaf(f0, cb[j],     i0 * g0);
                float c1 = fmaf(f1, cb[j + 1], i1 * g1);
                cb[j] = c0; cb[j + 1] = c1;
                float h0 = o0 * tanhap(c0);
                float h1 = o1 * tanhap(c1);

                int row = mt * 16 + gid + jr * 8;
                __half2 h2 = __floats2half2_rn(h0, h1);
                *(__half2*)&bufW[row * ASTRIDE + ownCol] = h2;
                uint32_t off = (uint32_t)((row * ASTRIDE + peerCol) * 2);
                uint32_t hv = *reinterpret_cast<uint32_t*>(&h2);
                asm volatile("st.shared::cluster.b32 [%0], %1;"
                             :: "r"(peerW + off), "r"(hv) : "memory");
            }
        }

        // stage x(t+1)
        if (t < 255)
            *(__half2*)&bufW[xrow * ASTRIDE + xdp] = __float22half2_rn(xnext);

        __syncthreads();               // all local+DSMEM stores drained
        if (tid == 0)                  // signal peer: buf[wb] peer-half ready,
            MBAR_ARRIVE_PEER(wb ? mbarP1 : mbarP0);  // my reads of buf[t] done
    }

    // ---- FC: out[b][f] = h_last . W_fc[f][:] + b_fc[f] ----
    // h_256 lives in buf0 (local order [own|peer]); wait peer's final arrive.
    MBAR_WAITP(mbarL0, 1);

    float accf[2][4];
#pragma unroll
    for (int mt = 0; mt < 2; mt++)
#pragma unroll
        for (int j = 0; j < 4; j++) accf[mt][j] = 0.0f;

    const uint2* __restrict__ fbase = g_Wfc2 + (s * 16) * 32 + l;
#pragma unroll 2
    for (int kc = 0; kc < 16; kc++) {
        uint2 B = __ldg(fbase + kc * 32);
#pragma unroll
        for (int mt = 0; mt < 2; mt++) {
            uint32_t a0, a1, a2, a3;
            LDMATRIX_X4(a0, a1, a2, a3,
                        aBase[0] + (uint32_t)((mt * 16 * ASTRIDE + 32 + kc * 16) * 2));
            MMA16816(accf[mt], a0, a1, a2, a3, B.x, B.y);
        }
    }

    {
        float2 bf = *(const float2*)&b_fc[fcCol];
#pragma unroll
        for (int mt = 0; mt < 2; mt++) {
#pragma unroll
            for (int jr = 0; jr < 2; jr++) {
                int row = b0 + mt * 16 + gid + jr * 8;
                float2 r;
                r.x = accf[mt][2 * jr]     + bf.x;
                r.y = accf[mt][2 * jr + 1] + bf.y;
                *(float2*)&out[(size_t)row * 256 + fcCol] = r;
            }
        }
    }

    CLUSTER_SYNC();   // no CTA exits while peer may still touch its smem
}

extern "C" void kernel_launch(void* const* d_in, const int* in_sizes, int n_in,
                              void* d_out, int out_size) {
    const float* obs  = (const float*)d_in[0];  // [2048,256,32]
    const float* W_ih = (const float*)d_in[1];  // [1024,32]
    const float* W_hh = (const float*)d_in[2];  // [1024,256]
    const float* b_ih = (const float*)d_in[3];  // [1024]
    const float* b_hh = (const float*)d_in[4];  // [1024]
    const float* W_fc = (const float*)d_in[5];  // [256,256]
    const float* b_fc = (const float*)d_in[6];  // [256]
    float* out = (float*)d_out;                 // [2048,256]

    cudaFuncSetAttribute(lstm_kernel,
                         cudaFuncAttributeMaxDynamicSharedMemorySize,
                         SMEM_TOTAL);

    int total = NSLOT * NKC * 2 * 32 + NSLOT * 16 * 32;   // 53248
    prep_kernel<<<(total + 255) / 256, 256>>>(W_ih, W_hh, W_fc);
    lstm_kernel<<<NCTA, 512, SMEM_TOTAL>>>(obs, b_ih, b_hh, b_fc, out);
}

// round 17
// speedup vs baseline: 2.1861x; 1.0372x over previous
#include <cuda_runtime.h>
#include <cuda_fp16.h>
#include <cstdint>

// LSTM extractor, HMMA m16n8k16 fp16/fp32, cluster-2 N-split.
//   B=2048, T=256, D=32, H=256, F=256.
// 128 CTAs (64 clusters of 2) x 512 threads. Cluster owns M=32 batch rows;
// CTA rank r computes all 4 gates for hidden units [128r, 128r+128).
// R15: resident smem weights for kc 0..9 (zero L2 for 10/18 of the stream).
// R16: activations via tanh.approx.f16x2 -> 20 MUFU warp-instrs per thread
//      per step instead of 40 (the MUFU burst is fully exposed because the
//      step barrier phase-locks all warps). c-state stays fp32.

#define NKC     18      // K chunks of 16 (K = 288 = 32 x + 256 h)
#define NRES    10      // resident K chunks (x + own h; kc>=10 is peer h)
#define ASTRIDE 296     // halves per A row (592B)
#define NSLOT   32      // 8-unit slots across the cluster
#define NCTA    128

__device__ uint4 g_W2[NSLOT * NKC * 2 * 32];   // per-slot fragment-major
__device__ uint2 g_Wfc2[NSLOT * 16 * 32];

struct SmemLayout {
    __half hA[2][32 * ASTRIDE];                // 37,888 B (double-buffered A)
    float bias[1024];                          //  4,096 B
    unsigned long long mbar[2];                //     16 B
    uint4 wres[16][NRES][2][32];               // 163,840 B resident weights
};
#define SMEM_TOTAL ((int)sizeof(SmemLayout))   // ~205,840 B

__device__ __forceinline__ __half2 tanh2(__half2 z) {
    uint32_t zi = *reinterpret_cast<uint32_t*>(&z);
    uint32_t r;
    asm("tanh.approx.f16x2 %0, %1;" : "=r"(r) : "r"(zi));
    return *reinterpret_cast<__half2*>(&r);
}
// sigmoid(x) = 0.5*tanh(0.5x) + 0.5, all in f16x2
__device__ __forceinline__ __half2 sig2(__half2 z) {
    const __half2 h05 = __halves2half2(__ushort_as_half(0x3800),
                                       __ushort_as_half(0x3800)); // 0.5
    __half2 t = tanh2(__hmul2(z, h05));
    return __hfma2(t, h05, h05);
}

__device__ __forceinline__ uint32_t smemu32(const void* p) {
    uint32_t a;
    asm("{ .reg .u64 t; cvta.to.shared.u64 t, %1; cvt.u32.u64 %0, t; }"
        : "=r"(a) : "l"(p));
    return a;
}
__device__ __forceinline__ uint32_t mapa_u32(uint32_t addr, uint32_t r) {
    uint32_t o;
    asm("mapa.shared::cluster.u32 %0, %1, %2;" : "=r"(o) : "r"(addr), "r"(r));
    return o;
}

#define MBAR_INIT(addr, cnt)                                                \
    asm volatile("mbarrier.init.shared.b64 [%0], %1;"                       \
                 :: "r"(addr), "r"(cnt) : "memory")

#define MBAR_ARRIVE_PEER(addr)                                              \
    asm volatile("mbarrier.arrive.release.cluster.shared::cluster.b64 _, [%0];" \
                 :: "r"(addr) : "memory")

#define MBAR_WAITP(addr, phase)                                             \
    asm volatile("{\n\t.reg .pred P;\n\t"                                   \
        "WL%=:\n\t"                                                         \
        "mbarrier.try_wait.parity.acquire.cluster.shared::cta.b64 P, [%0], %1;\n\t" \
        "@P bra WD%=;\n\tbra WL%=;\n\tWD%=:\n\t}"                           \
        :: "r"(addr), "r"(phase) : "memory")

#define CLUSTER_SYNC() do {                                                 \
    asm volatile("barrier.cluster.arrive.aligned;" ::: "memory");           \
    asm volatile("barrier.cluster.wait.aligned;" ::: "memory");             \
} while (0)

#define LDMATRIX_X4(a0, a1, a2, a3, addr)                                   \
    asm volatile("ldmatrix.sync.aligned.m8n8.x4.shared.b16 {%0,%1,%2,%3}, [%4];" \
                 : "=r"(a0), "=r"(a1), "=r"(a2), "=r"(a3) : "r"(addr))

#define MMA16816(d, a0, a1, a2, a3, b0, b1)                                 \
    asm volatile("mma.sync.aligned.m16n8k16.row.col.f32.f16.f16.f32 "       \
                 "{%0,%1,%2,%3},{%4,%5,%6,%7},{%8,%9},{%0,%1,%2,%3};"       \
                 : "+f"(d[0]), "+f"(d[1]), "+f"(d[2]), "+f"(d[3])           \
                 : "r"(a0), "r"(a1), "r"(a2), "r"(a3), "r"(b0), "r"(b1))

// ---------------- prep: weights -> per-slot fp16 fragment layouts ---------
__device__ __forceinline__ float wval(const float* W_ih, const float* W_hh,
                                      int col, int k) {
    return (k < 32) ? W_ih[col * 32 + k] : W_hh[col * 256 + (k - 32)];
}
// local K index -> global K index for rank-local A layout [x|own-h|peer-h]
__device__ __forceinline__ int kmap(int rank, int kk) {
    if (kk < 32) return kk;
    int p = kk - 32;
    int gu = (p < 128) ? rank * 128 + p : (rank ^ 1) * 128 + (p - 128);
    return 32 + gu;
}
__device__ __forceinline__ int gumap(int rank, int p) {   // FC h position
    return (p < 128) ? rank * 128 + p : (rank ^ 1) * 128 + (p - 128);
}

__global__ void prep_kernel(const float* __restrict__ W_ih,
                            const float* __restrict__ W_hh,
                            const float* __restrict__ W_fc) {
    int g = blockIdx.x * 256 + threadIdx.x;
    if (g < NSLOT * NKC * 2 * 32) {                 // 36864
        int l = g & 31;
        int t = g >> 5;
        int q = t & 1;  t >>= 1;
        int kc = t % NKC;
        int s  = t / NKC;
        int rank = s >> 4;
        int k0 = kc * 16 + (l & 3) * 2;
        int n  = l >> 2;
        union { __half h[8]; uint4 v; } u;
        for (int hf = 0; hf < 2; hf++) {
            int gate = 2 * q + hf;                  // 0=i 1=f 2=g 3=o
            int col = gate * 256 + s * 8 + n;
            u.h[hf * 4 + 0] = __float2half(wval(W_ih, W_hh, col, kmap(rank, k0)));
            u.h[hf * 4 + 1] = __float2half(wval(W_ih, W_hh, col, kmap(rank, k0 + 1)));
            u.h[hf * 4 + 2] = __float2half(wval(W_ih, W_hh, col, kmap(rank, k0 + 8)));
            u.h[hf * 4 + 3] = __float2half(wval(W_ih, W_hh, col, kmap(rank, k0 + 9)));
        }
        g_W2[g] = u.v;
    } else if (g < NSLOT * NKC * 2 * 32 + NSLOT * 16 * 32) {   // +16384
        int g2 = g - NSLOT * NKC * 2 * 32;
        int l = g2 & 31;
        int t = g2 >> 5;
        int kc = t & 15;
        int s  = t >> 4;
        int rank = s >> 4;
        int k0 = kc * 16 + (l & 3) * 2;
        int n  = l >> 2;
        int col = s * 8 + n;
        union { __half h[4]; uint2 v; } u;
        u.h[0] = __float2half(W_fc[col * 256 + gumap(rank, k0)]);
        u.h[1] = __float2half(W_fc[col * 256 + gumap(rank, k0 + 1)]);
        u.h[2] = __float2half(W_fc[col * 256 + gumap(rank, k0 + 8)]);
        u.h[3] = __float2half(W_fc[col * 256 + gumap(rank, k0 + 9)]);
        g_Wfc2[g2] = u.v;
    }
}

// ---------------- main persistent LSTM + FC kernel ------------------------
__global__ void __launch_bounds__(512, 1) __cluster_dims__(2, 1, 1)
lstm_kernel(const float* __restrict__ obs,
            const float* __restrict__ b_ih,
            const float* __restrict__ b_hh,
            const float* __restrict__ b_fc,
            float* __restrict__ out) {
    extern __shared__ __align__(16) char smem_raw[];
    SmemLayout& S = *reinterpret_cast<SmemLayout*>(smem_raw);

    const int tid  = threadIdx.x;
    const int w    = tid >> 5;
    const int l    = tid & 31;
    const int gid  = l >> 2;
    const int tid4 = l & 3;

    uint32_t rank;
    asm("mov.u32 %0, %%cluster_ctarank;" : "=r"(rank));
    const int s  = (int)rank * 16 + w;     // global 8-unit slot
    const int b0 = (blockIdx.x >> 1) * 32; // cluster's first batch row

    const uint32_t mbarL0 = smemu32(&S.mbar[0]);
    const uint32_t mbarL1 = smemu32(&S.mbar[1]);
    const uint32_t mbarP0 = mapa_u32(mbarL0, rank ^ 1u);
    const uint32_t mbarP1 = mapa_u32(mbarL1, rank ^ 1u);
    if (tid == 0) {
        MBAR_INIT(mbarL0, 1);
        MBAR_INIT(mbarL1, 1);
    }

    S.bias[tid]       = b_ih[tid]       + b_hh[tid];
    S.bias[tid + 512] = b_ih[tid + 512] + b_hh[tid + 512];

    // zero buf0 (h regions must start at 0); buf1 fully written in step 0
    for (int i = tid; i < 32 * ASTRIDE; i += 512)
        S.hA[0][i] = __float2half(0.0f);

    const uint4* __restrict__ wbase = g_W2 + (s * NKC * 2) * 32 + l;

    // load my resident weight slice (kc 0..9). Writer == reader thread.
#pragma unroll
    for (int kc = 0; kc < NRES; kc++) {
        S.wres[w][kc][0][l] = __ldg(wbase + (kc * 2    ) * 32);
        S.wres[w][kc][1][l] = __ldg(wbase + (kc * 2 + 1) * 32);
    }

    // x staging role: thread -> (row, feature pair)
    const int xrow = tid >> 4;
    const int xdp  = (tid & 15) * 2;
    const float* xptr = obs + (size_t)(b0 + xrow) * 8192 + xdp;
    {   // stage x(0) into buf0
        float2 x2 = *(const float2*)xptr;
        *(__half2*)&S.hA[0][xrow * ASTRIDE + xdp] = __float22half2_rn(x2);
    }
    __syncthreads();
    CLUSTER_SYNC();   // once: peer mbar init visible before any arrive

    const uint32_t locA0 = smemu32(S.hA[0]);
    const uint32_t locA1 = smemu32(S.hA[1]);
    uint32_t peerA[2];
    peerA[0] = mapa_u32(locA0, rank ^ 1u);
    peerA[1] = mapa_u32(locA1, rank ^ 1u);

    float c[8];
#pragma unroll
    for (int i = 0; i < 8; i++) c[i] = 0.0f;

    const uint32_t aoff = (uint32_t)(((l & 15) * ASTRIDE + (l >> 4) * 8) * 2);
    const uint32_t aBase[2] = { locA0 + aoff, locA1 + aoff };

    float2 bsv[4];
#pragma unroll
    for (int gate = 0; gate < 4; gate++)
        bsv[gate] = *(const float2*)&S.bias[gate * 256 + s * 8 + tid4 * 2];

    const int ownCol  = 32 + w * 8 + tid4 * 2;    // my h cols in MY buffer
    const int peerCol = 160 + w * 8 + tid4 * 2;   // my h cols in PEER buffer
    const int fcCol   = s * 8 + tid4 * 2;         // FC output feature pair

    const uint4* __restrict__ wres = &S.wres[w][0][0][l];   // stride 32 per q

#pragma unroll 1
    for (int t = 0; t < 256; t++) {
        const uint32_t aR = aBase[t & 1];
        const int wb = (t + 1) & 1;
        __half* __restrict__ bufW = S.hA[wb];
        const uint32_t peerW = peerA[wb];

        // issue streamed-weight ring (kc 10..12) NOW: covered by the whole
        // resident phase before first consumption.
        uint4 R[3][2];
#pragma unroll
        for (int q = 0; q < 3; q++) {
            R[q][0] = __ldg(wbase + ((10 + q) * 2    ) * 32);
            R[q][1] = __ldg(wbase + ((10 + q) * 2 + 1) * 32);
        }

        // prefetch x(t+1) (overlaps GEMM)
        float2 xnext;
        if (t < 255) xnext = *(const float2*)(xptr + (size_t)(t + 1) * 32);

        float acc0[4][4], acc1[4][4];
#pragma unroll
        for (int gate = 0; gate < 4; gate++) {
            acc0[gate][0] = bsv[gate].x; acc0[gate][1] = bsv[gate].y;
            acc0[gate][2] = bsv[gate].x; acc0[gate][3] = bsv[gate].y;
            acc1[gate][0] = bsv[gate].x; acc1[gate][1] = bsv[gate].y;
            acc1[gate][2] = bsv[gate].x; acc1[gate][3] = bsv[gate].y;
        }

        // --- resident K: kc 0..9 (x + own h), both mt; B via LDS.128 ---
#pragma unroll
        for (int kc = 0; kc < NRES; kc++) {
            const uint4 B0 = wres[(kc * 2    ) * 32];
            const uint4 B1 = wres[(kc * 2 + 1) * 32];
            uint32_t a0, a1, a2, a3;
            LDMATRIX_X4(a0, a1, a2, a3,
                        aR + (uint32_t)((kc * 16) * 2));
            MMA16816(acc0[0], a0, a1, a2, a3, B0.x, B0.y);
            MMA16816(acc0[1], a0, a1, a2, a3, B0.z, B0.w);
            MMA16816(acc0[2], a0, a1, a2, a3, B1.x, B1.y);
            MMA16816(acc0[3], a0, a1, a2, a3, B1.z, B1.w);
            LDMATRIX_X4(a0, a1, a2, a3,
                        aR + (uint32_t)((16 * ASTRIDE + kc * 16) * 2));
            MMA16816(acc1[0], a0, a1, a2, a3, B0.x, B0.y);
            MMA16816(acc1[1], a0, a1, a2, a3, B0.z, B0.w);
            MMA16816(acc1[2], a0, a1, a2, a3, B1.x, B1.y);
            MMA16816(acc1[3], a0, a1, a2, a3, B1.z, B1.w);
        }

        // --- wait for peer's h-half of this step's A buffer ---
        if (t > 0) {
            int phase = ((t - 2 + (t & 1)) >> 1) & 1;
            MBAR_WAITP((t & 1) ? mbarL1 : mbarL0, phase);
        }

        // --- streamed K: kc 10..17 (peer h), both mt; ring depth 3 ---
#pragma unroll
        for (int kc = 10; kc < NKC; kc++) {
            const uint4 B0 = R[(kc - 10) % 3][0];
            const uint4 B1 = R[(kc - 10) % 3][1];
            if (kc + 3 < NKC) {
                const uint4* wn = wbase + ((kc + 3) * 2) * 32;
                R[(kc - 10) % 3][0] = __ldg(wn);
                R[(kc - 10) % 3][1] = __ldg(wn + 32);
            }
            uint32_t a0, a1, a2, a3;
            LDMATRIX_X4(a0, a1, a2, a3,
                        aR + (uint32_t)((kc * 16) * 2));
            MMA16816(acc0[0], a0, a1, a2, a3, B0.x, B0.y);
            MMA16816(acc0[1], a0, a1, a2, a3, B0.z, B0.w);
            MMA16816(acc0[2], a0, a1, a2, a3, B1.x, B1.y);
            MMA16816(acc0[3], a0, a1, a2, a3, B1.z, B1.w);
            LDMATRIX_X4(a0, a1, a2, a3,
                        aR + (uint32_t)((16 * ASTRIDE + kc * 16) * 2));
            MMA16816(acc1[0], a0, a1, a2, a3, B0.x, B0.y);
            MMA16816(acc1[1], a0, a1, a2, a3, B0.z, B0.w);
            MMA16816(acc1[2], a0, a1, a2, a3, B1.x, B1.y);
            MMA16816(acc1[3], a0, a1, a2, a3, B1.z, B1.w);
        }

        // gates (f16x2 MUFU) + fp32 c update; publish h local + peer DSMEM
#pragma unroll
        for (int mt = 0; mt < 2; mt++) {
            float* acc = mt ? &acc1[0][0] : &acc0[0][0];
            float* cb  = c + mt * 4;
#pragma unroll
            for (int jr = 0; jr < 2; jr++) {
                int j = 2 * jr;
                __half2 zi = __floats2half2_rn(acc[0 * 4 + j], acc[0 * 4 + j + 1]);
                __half2 zf = __floats2half2_rn(acc[1 * 4 + j], acc[1 * 4 + j + 1]);
                __half2 zg = __floats2half2_rn(acc[2 * 4 + j], acc[2 * 4 + j + 1]);
                __half2 zo = __floats2half2_rn(acc[3 * 4 + j], acc[3 * 4 + j + 1]);
                __half2 i2 = sig2(zi);
                __half2 f2 = sig2(zf);
                __half2 g2 = tanh2(zg);
                __half2 o2 = sig2(zo);

                float c0 = fmaf(__low2float(f2),  cb[j],
                                __low2float(i2)  * __low2float(g2));
                float c1 = fmaf(__high2float(f2), cb[j + 1],
                                __high2float(i2) * __high2float(g2));
                cb[j] = c0; cb[j + 1] = c1;

                __half2 tc = tanh2(__floats2half2_rn(c0, c1));
                __half2 h2 = __hmul2(o2, tc);

                int row = mt * 16 + gid + jr * 8;
                *(__half2*)&bufW[row * ASTRIDE + ownCol] = h2;
                uint32_t off = (uint32_t)((row * ASTRIDE + peerCol) * 2);
                uint32_t hv = *reinterpret_cast<uint32_t*>(&h2);
                asm volatile("st.shared::cluster.b32 [%0], %1;"
                             :: "r"(peerW + off), "r"(hv) : "memory");
            }
        }

        // stage x(t+1)
        if (t < 255)
            *(__half2*)&bufW[xrow * ASTRIDE + xdp] = __float22half2_rn(xnext);

        __syncthreads();               // all local+DSMEM stores drained
        if (tid == 0)                  // signal peer: buf[wb] peer-half ready,
            MBAR_ARRIVE_PEER(wb ? mbarP1 : mbarP0);  // my reads of buf[t] done
    }

    // ---- FC: out[b][f] = h_last . W_fc[f][:] + b_fc[f] ----
    // h_256 lives in buf0 (local order [own|peer]); wait peer's final arrive.
    MBAR_WAITP(mbarL0, 1);

    float accf[2][4];
#pragma unroll
    for (int mt = 0; mt < 2; mt++)
#pragma unroll
        for (int j = 0; j < 4; j++) accf[mt][j] = 0.0f;

    const uint2* __restrict__ fbase = g_Wfc2 + (s * 16) * 32 + l;
#pragma unroll 2
    for (int kc = 0; kc < 16; kc++) {
        uint2 B = __ldg(fbase + kc * 32);
#pragma unroll
        for (int mt = 0; mt < 2; mt++) {
            uint32_t a0, a1, a2, a3;
            LDMATRIX_X4(a0, a1, a2, a3,
                        aBase[0] + (uint32_t)((mt * 16 * ASTRIDE + 32 + kc * 16) * 2));
            MMA16816(accf[mt], a0, a1, a2, a3, B.x, B.y);
        }
    }

    {
        float2 bf = *(const float2*)&b_fc[fcCol];
#pragma unroll
        for (int mt = 0; mt < 2; mt++) {
#pragma unroll
            for (int jr = 0; jr < 2; jr++) {
                int row = b0 + mt * 16 + gid + jr * 8;
                float2 r;
                r.x = accf[mt][2 * jr]     + bf.x;
                r.y = accf[mt][2 * jr + 1] + bf.y;
                *(float2*)&out[(size_t)row * 256 + fcCol] = r;
            }
        }
    }

    CLUSTER_SYNC();   // no CTA exits while peer may still touch its smem
}

extern "C" void kernel_launch(void* const* d_in, const int* in_sizes, int n_in,
                              void* d_out, int out_size) {
    const float* obs  = (const float*)d_in[0];  // [2048,256,32]
    const float* W_ih = (const float*)d_in[1];  // [1024,32]
    const float* W_hh = (const float*)d_in[2];  // [1024,256]
    const float* b_ih = (const float*)d_in[3];  // [1024]
    const float* b_hh = (const float*)d_in[4];  // [1024]
    const float* W_fc = (const float*)d_in[5];  // [256,256]
    const float* b_fc = (const float*)d_in[6];  // [256]
    float* out = (float*)d_out;                 // [2048,256]

    cudaFuncSetAttribute(lstm_kernel,
                         cudaFuncAttributeMaxDynamicSharedMemorySize,
                         SMEM_TOTAL);

    int total = NSLOT * NKC * 2 * 32 + NSLOT * 16 * 32;   // 53248
    prep_kernel<<<(total + 255) / 256, 256>>>(W_ih, W_hh, W_fc);
    lstm_kernel<<<NCTA, 512, SMEM_TOTAL>>>(obs, b_ih, b_hh, b_fc, out);
}